// round 1
// baseline (speedup 1.0000x reference)
#include <cuda_runtime.h>

#define BATCH  4
#define CHN    256
#define NTOK   4096      // 64*64 spatial
#define GROUPS 32
#define CPG    8         // channels per group
#define EPS    1e-5f

// ---------------- scratch (no allocations allowed) ----------------
__device__ float g_xn [BATCH * CHN * NTOK];            // 16 MB  group-normed x, [b][c][n]
__device__ float g_qkv[BATCH * 3 * CHN * NTOK];        // 48 MB  [b][o][n], o in 0..767
__device__ float g_attn[(size_t)BATCH * NTOK * NTOK];  // 256 MB scores/probs [b][n][m]
__device__ float g_ao [BATCH * CHN * NTOK];            // 16 MB  attn output [b][c][n]

// ---------------- GroupNorm ----------------
// one block per (b, g): 8 channels * 4096 = 32768 elems
__global__ __launch_bounds__(256) void gn_kernel(const float* __restrict__ x,
                                                 const float* __restrict__ w,
                                                 const float* __restrict__ bias) {
    int b = blockIdx.x >> 5;
    int g = blockIdx.x & 31;
    size_t base = ((size_t)b * CHN + g * CPG) * NTOK;
    const float4* xv = (const float4*)(x + base);
    float4* ov = (float4*)(g_xn + base);
    const int NV = CPG * NTOK / 4;  // 8192 float4

    float s = 0.f, ss = 0.f;
    for (int i = threadIdx.x; i < NV; i += 256) {
        float4 v = xv[i];
        s  += v.x + v.y + v.z + v.w;
        ss += v.x * v.x + v.y * v.y + v.z * v.z + v.w * v.w;
    }
    __shared__ float rs[256], rss[256];
    rs[threadIdx.x] = s; rss[threadIdx.x] = ss;
    __syncthreads();
    for (int st = 128; st > 0; st >>= 1) {
        if (threadIdx.x < st) {
            rs[threadIdx.x]  += rs[threadIdx.x + st];
            rss[threadIdx.x] += rss[threadIdx.x + st];
        }
        __syncthreads();
    }
    float mean = rs[0] * (1.f / 32768.f);
    float var  = rss[0] * (1.f / 32768.f) - mean * mean;
    float rstd = rsqrtf(var + EPS);

    for (int i = threadIdx.x; i < NV; i += 256) {
        int ch = g * CPG + (i >> 10);   // 1024 float4 per channel
        float sc = w[ch] * rstd;
        float sh = bias[ch] - mean * sc;
        float4 v = xv[i];
        v.x = v.x * sc + sh; v.y = v.y * sc + sh;
        v.z = v.z * sc + sh; v.w = v.w * sc + sh;
        ov[i] = v;
    }
}

// ---------------- QKV projection ----------------
// g_qkv[b][o][n] = sum_c W[o][c] * g_xn[b][c][n] + bias[o]
// grid (NTOK/64, 768/64, BATCH), block 256, 64x64 tile, BK=16, 4x4 micro
__global__ __launch_bounds__(256) void qkv_gemm(const float* __restrict__ W,
                                                const float* __restrict__ bias) {
    const int n0 = blockIdx.x * 64;
    const int m0 = blockIdx.y * 64;
    const int b  = blockIdx.z;
    const float* Xb = g_xn + (size_t)b * CHN * NTOK;
    float* Ob = g_qkv + (size_t)b * 3 * CHN * NTOK;

    __shared__ float As[16][68];   // k-major [k][m]
    __shared__ float Bs[16][68];   // k-major [k][n]
    const int tid = threadIdx.x;
    const int tx = tid & 15, ty = tid >> 4;
    float acc[4][4] = {};

    for (int k0 = 0; k0 < CHN; k0 += 16) {
        {   // A: W tile 64(m) x 16(k), transpose into As[k][m]
            int kk = tid & 15, r0 = tid >> 4;
            #pragma unroll
            for (int rr = 0; rr < 4; rr++)
                As[kk][r0 + rr * 16] = W[(size_t)(m0 + r0 + rr * 16) * CHN + k0 + kk];
        }
        {   // B: X tile 16(k) x 64(n)
            int c = tid & 63, kb = tid >> 6;
            #pragma unroll
            for (int rr = 0; rr < 4; rr++)
                Bs[kb + rr * 4][c] = Xb[(size_t)(k0 + kb + rr * 4) * NTOK + n0 + c];
        }
        __syncthreads();
        #pragma unroll
        for (int k = 0; k < 16; k++) {
            float4 a  = *(const float4*)&As[k][ty * 4];
            float4 bv = *(const float4*)&Bs[k][tx * 4];
            float av[4] = {a.x, a.y, a.z, a.w};
            float bb[4] = {bv.x, bv.y, bv.z, bv.w};
            #pragma unroll
            for (int i = 0; i < 4; i++)
                #pragma unroll
                for (int j = 0; j < 4; j++) acc[i][j] += av[i] * bb[j];
        }
        __syncthreads();
    }
    #pragma unroll
    for (int i = 0; i < 4; i++) {
        int m = m0 + ty * 4 + i;
        float bb = bias[m];
        float4 o = make_float4(acc[i][0] + bb, acc[i][1] + bb,
                               acc[i][2] + bb, acc[i][3] + bb);
        *(float4*)&Ob[(size_t)m * NTOK + n0 + tx * 4] = o;
    }
}

// ---------------- scores = scale * Q^T K ----------------
// g_attn[b][n][m] = (1/16) * sum_c Q[c][n] * K[c][m]
// Q, K both [c][n] layout -> TN gemm, no transpose staging needed
__global__ __launch_bounds__(256) void scores_gemm() {
    const int m0 = blockIdx.x * 64;   // key index (cols)
    const int n0 = blockIdx.y * 64;   // query index (rows)
    const int b  = blockIdx.z;
    const float* Q  = g_qkv + (size_t)b * 3 * CHN * NTOK;
    const float* Kp = Q + (size_t)CHN * NTOK;
    float* S = g_attn + (size_t)b * NTOK * NTOK;

    __shared__ float As[16][68];   // [k][n]
    __shared__ float Bs[16][68];   // [k][m]
    const int tid = threadIdx.x;
    const int tx = tid & 15, ty = tid >> 4;
    float acc[4][4] = {};

    for (int k0 = 0; k0 < CHN; k0 += 16) {
        int c = tid & 63, kb = tid >> 6;
        #pragma unroll
        for (int rr = 0; rr < 4; rr++) {
            As[kb + rr * 4][c] = Q [(size_t)(k0 + kb + rr * 4) * NTOK + n0 + c];
            Bs[kb + rr * 4][c] = Kp[(size_t)(k0 + kb + rr * 4) * NTOK + m0 + c];
        }
        __syncthreads();
        #pragma unroll
        for (int k = 0; k < 16; k++) {
            float4 a  = *(const float4*)&As[k][ty * 4];
            float4 bv = *(const float4*)&Bs[k][tx * 4];
            float av[4] = {a.x, a.y, a.z, a.w};
            float bb[4] = {bv.x, bv.y, bv.z, bv.w};
            #pragma unroll
            for (int i = 0; i < 4; i++)
                #pragma unroll
                for (int j = 0; j < 4; j++) acc[i][j] += av[i] * bb[j];
        }
        __syncthreads();
    }
    const float scale = 0.0625f;  // 256^-0.5
    #pragma unroll
    for (int i = 0; i < 4; i++) {
        int n = n0 + ty * 4 + i;
        float4 o = make_float4(acc[i][0] * scale, acc[i][1] * scale,
                               acc[i][2] * scale, acc[i][3] * scale);
        *(float4*)&S[(size_t)n * NTOK + m0 + tx * 4] = o;
    }
}

// ---------------- softmax over m, register-resident row ----------------
__global__ __launch_bounds__(256) void softmax_kernel() {
    size_t row = blockIdx.x;                   // b*NTOK + n
    float4* pv = (float4*)(g_attn + row * NTOK);
    const int t = threadIdx.x;
    float4 v[4];
    float mx = -1e30f;
    #pragma unroll
    for (int i = 0; i < 4; i++) {
        v[i] = pv[t + i * 256];
        mx = fmaxf(mx, fmaxf(fmaxf(v[i].x, v[i].y), fmaxf(v[i].z, v[i].w)));
    }
    __shared__ float red[256];
    red[t] = mx; __syncthreads();
    for (int st = 128; st > 0; st >>= 1) {
        if (t < st) red[t] = fmaxf(red[t], red[t + st]);
        __syncthreads();
    }
    mx = red[0];
    __syncthreads();
    float s = 0.f;
    #pragma unroll
    for (int i = 0; i < 4; i++) {
        v[i].x = __expf(v[i].x - mx); v[i].y = __expf(v[i].y - mx);
        v[i].z = __expf(v[i].z - mx); v[i].w = __expf(v[i].w - mx);
        s += v[i].x + v[i].y + v[i].z + v[i].w;
    }
    red[t] = s; __syncthreads();
    for (int st = 128; st > 0; st >>= 1) {
        if (t < st) red[t] += red[t + st];
        __syncthreads();
    }
    float inv = 1.f / red[0];
    #pragma unroll
    for (int i = 0; i < 4; i++) {
        v[i].x *= inv; v[i].y *= inv; v[i].z *= inv; v[i].w *= inv;
        pv[t + i * 256] = v[i];
    }
}

// ---------------- attn @ V ----------------
// g_ao[b][c][n] = sum_m V[c][m] * P[n][m]   (NT gemm, K=4096)
__global__ __launch_bounds__(256) void av_gemm() {
    const int n0 = blockIdx.x * 64;   // token (cols)
    const int c0 = blockIdx.y * 64;   // channel (rows)
    const int b  = blockIdx.z;
    const float* V = g_qkv + (size_t)b * 3 * CHN * NTOK + (size_t)2 * CHN * NTOK;
    const float* P = g_attn + (size_t)b * NTOK * NTOK;
    float* O = g_ao + (size_t)b * CHN * NTOK;

    __shared__ float As[16][68];   // [k][c]
    __shared__ float Bs[16][68];   // [k][n]
    const int tid = threadIdx.x;
    const int tx = tid & 15, ty = tid >> 4;
    float acc[4][4] = {};

    for (int k0 = 0; k0 < NTOK; k0 += 16) {
        int kk = tid & 15, r0 = tid >> 4;
        #pragma unroll
        for (int rr = 0; rr < 4; rr++) {
            As[kk][r0 + rr * 16] = V[(size_t)(c0 + r0 + rr * 16) * NTOK + k0 + kk];
            Bs[kk][r0 + rr * 16] = P[(size_t)(n0 + r0 + rr * 16) * NTOK + k0 + kk];
        }
        __syncthreads();
        #pragma unroll
        for (int k = 0; k < 16; k++) {
            float4 a  = *(const float4*)&As[k][ty * 4];
            float4 bv = *(const float4*)&Bs[k][tx * 4];
            float av[4] = {a.x, a.y, a.z, a.w};
            float bb[4] = {bv.x, bv.y, bv.z, bv.w};
            #pragma unroll
            for (int i = 0; i < 4; i++)
                #pragma unroll
                for (int j = 0; j < 4; j++) acc[i][j] += av[i] * bb[j];
        }
        __syncthreads();
    }
    #pragma unroll
    for (int i = 0; i < 4; i++) {
        int c = c0 + ty * 4 + i;
        float4 o = make_float4(acc[i][0], acc[i][1], acc[i][2], acc[i][3]);
        *(float4*)&O[(size_t)c * NTOK + n0 + tx * 4] = o;
    }
}

// ---------------- output projection + bias + residual ----------------
// y[b][o][n] = sum_c W[o][c] * g_ao[b][c][n] + bias[o] + x[b][o][n]
__global__ __launch_bounds__(256) void proj_gemm(const float* __restrict__ W,
                                                 const float* __restrict__ bias,
                                                 const float* __restrict__ x,
                                                 float* __restrict__ y) {
    const int n0 = blockIdx.x * 64;
    const int m0 = blockIdx.y * 64;
    const int b  = blockIdx.z;
    const float* Xb = g_ao + (size_t)b * CHN * NTOK;
    const float* Rb = x + (size_t)b * CHN * NTOK;
    float* Ob = y + (size_t)b * CHN * NTOK;

    __shared__ float As[16][68];
    __shared__ float Bs[16][68];
    const int tid = threadIdx.x;
    const int tx = tid & 15, ty = tid >> 4;
    float acc[4][4] = {};

    for (int k0 = 0; k0 < CHN; k0 += 16) {
        {
            int kk = tid & 15, r0 = tid >> 4;
            #pragma unroll
            for (int rr = 0; rr < 4; rr++)
                As[kk][r0 + rr * 16] = W[(size_t)(m0 + r0 + rr * 16) * CHN + k0 + kk];
        }
        {
            int c = tid & 63, kb = tid >> 6;
            #pragma unroll
            for (int rr = 0; rr < 4; rr++)
                Bs[kb + rr * 4][c] = Xb[(size_t)(k0 + kb + rr * 4) * NTOK + n0 + c];
        }
        __syncthreads();
        #pragma unroll
        for (int k = 0; k < 16; k++) {
            float4 a  = *(const float4*)&As[k][ty * 4];
            float4 bv = *(const float4*)&Bs[k][tx * 4];
            float av[4] = {a.x, a.y, a.z, a.w};
            float bb[4] = {bv.x, bv.y, bv.z, bv.w};
            #pragma unroll
            for (int i = 0; i < 4; i++)
                #pragma unroll
                for (int j = 0; j < 4; j++) acc[i][j] += av[i] * bb[j];
        }
        __syncthreads();
    }
    #pragma unroll
    for (int i = 0; i < 4; i++) {
        int m = m0 + ty * 4 + i;
        float bb = bias[m];
        float4 r = *(const float4*)&Rb[(size_t)m * NTOK + n0 + tx * 4];
        float4 o = make_float4(acc[i][0] + bb + r.x, acc[i][1] + bb + r.y,
                               acc[i][2] + bb + r.z, acc[i][3] + bb + r.w);
        *(float4*)&Ob[(size_t)m * NTOK + n0 + tx * 4] = o;
    }
}

// ---------------- launch ----------------
extern "C" void kernel_launch(void* const* d_in, const int* in_sizes, int n_in,
                              void* d_out, int out_size) {
    const float* x    = (const float*)d_in[0];
    const float* gnw  = (const float*)d_in[1];
    const float* gnb  = (const float*)d_in[2];
    const float* qkvw = (const float*)d_in[3];
    const float* qkvb = (const float*)d_in[4];
    const float* ow   = (const float*)d_in[5];
    const float* ob   = (const float*)d_in[6];
    float* y = (float*)d_out;

    gn_kernel   <<<BATCH * GROUPS, 256>>>(x, gnw, gnb);
    qkv_gemm    <<<dim3(NTOK / 64, (3 * CHN) / 64, BATCH), 256>>>(qkvw, qkvb);
    scores_gemm <<<dim3(NTOK / 64, NTOK / 64, BATCH), 256>>>();
    softmax_kernel<<<BATCH * NTOK, 256>>>();
    av_gemm     <<<dim3(NTOK / 64, CHN / 64, BATCH), 256>>>();
    proj_gemm   <<<dim3(NTOK / 64, CHN / 64, BATCH), 256>>>(ow, ob, x, y);
}

// round 3
// speedup vs baseline: 1.9642x; 1.9642x over previous
#include <cuda_runtime.h>
#include <cuda_bf16.h>
#include <cstdint>

#define BATCH 4
#define CHN   256
#define NTOK  4096
#define EPS   1e-5f

typedef __nv_bfloat16 bf16;

// ------------------------------------------------------------------
// scratch (__device__ globals; no allocations allowed)
// ------------------------------------------------------------------
__device__ bf16 g_xnh[(size_t)BATCH*NTOK*CHN];   // groupnormed x hi [b][n][c]
__device__ bf16 g_xnl[(size_t)BATCH*NTOK*CHN];
__device__ bf16 g_qh [(size_t)BATCH*NTOK*CHN];   // Q split [b][n][c]
__device__ bf16 g_ql [(size_t)BATCH*NTOK*CHN];
__device__ bf16 g_kh [(size_t)BATCH*NTOK*CHN];   // K split [b][m][c]
__device__ bf16 g_kl [(size_t)BATCH*NTOK*CHN];
__device__ bf16 g_vh [(size_t)BATCH*CHN*NTOK];   // V split [b][c][m]
__device__ bf16 g_vl [(size_t)BATCH*CHN*NTOK];
__device__ float g_attn[(size_t)BATCH*NTOK*NTOK];// scores fp32 [b][n][m]
__device__ bf16 g_ph[(size_t)BATCH*NTOK*NTOK];   // probs split [b][n][m]
__device__ bf16 g_pl[(size_t)BATCH*NTOK*NTOK];
__device__ bf16 g_aoh[(size_t)BATCH*NTOK*CHN];   // attn-out split [b][n][c]
__device__ bf16 g_aol[(size_t)BATCH*NTOK*CHN];
__device__ bf16 g_wqh[3*CHN*CHN], g_wql[3*CHN*CHN];
__device__ bf16 g_woh[CHN*CHN],   g_wol[CHN*CHN];

// ------------------------------------------------------------------
__device__ __forceinline__ uint32_t smem_u32(const void* p) {
    uint32_t a;
    asm("{ .reg .u64 t; cvta.to.shared.u64 t, %1; cvt.u32.u64 %0, t; }" : "=r"(a) : "l"(p));
    return a;
}
__device__ __forceinline__ void ldsm_x4(uint32_t& r0, uint32_t& r1, uint32_t& r2,
                                        uint32_t& r3, uint32_t addr) {
    asm volatile("ldmatrix.sync.aligned.m8n8.x4.shared.b16 {%0,%1,%2,%3}, [%4];"
                 : "=r"(r0), "=r"(r1), "=r"(r2), "=r"(r3) : "r"(addr));
}
__device__ __forceinline__ void mma_bf16(float* c, uint32_t a0, uint32_t a1,
                                         uint32_t a2, uint32_t a3,
                                         uint32_t b0, uint32_t b1) {
    asm volatile("mma.sync.aligned.m16n8k16.row.col.f32.bf16.bf16.f32 "
                 "{%0,%1,%2,%3}, {%4,%5,%6,%7}, {%8,%9}, {%0,%1,%2,%3};"
                 : "+f"(c[0]), "+f"(c[1]), "+f"(c[2]), "+f"(c[3])
                 : "r"(a0), "r"(a1), "r"(a2), "r"(a3), "r"(b0), "r"(b1));
}
__device__ __forceinline__ uint32_t pk2(bf16 a, bf16 b) {
    __nv_bfloat162 t; t.x = a; t.y = b;
    return *reinterpret_cast<uint32_t*>(&t);
}
__device__ __forceinline__ void split2(float v, bf16& h, bf16& l) {
    h = __float2bfloat16(v);
    l = __float2bfloat16(v - __bfloat162float(h));
}

// SMEM geometry: tiles A/B [128][40] bf16 each; epilogue stg [128][132] fp32 (union)
#define TPAD 40
#define SPAD 132
#define SMEM_BYTES (128 * SPAD * 4)   // 67584 >= 2*128*40*2 = 20480

// ------------------------------------------------------------------
// GroupNorm -> split bf16 token-major [b][n][c]
// ------------------------------------------------------------------
__global__ __launch_bounds__(256) void gn_kernel(const float* __restrict__ x,
                                                 const float* __restrict__ w,
                                                 const float* __restrict__ bias) {
    int b = blockIdx.x >> 5;
    int g = blockIdx.x & 31;
    size_t base = ((size_t)b * CHN + g * 8) * NTOK;
    const float4* xv = (const float4*)(x + base);
    const int NV = 8 * NTOK / 4;

    float s = 0.f, ss = 0.f;
    for (int i = threadIdx.x; i < NV; i += 256) {
        float4 v = xv[i];
        s  += v.x + v.y + v.z + v.w;
        ss += v.x*v.x + v.y*v.y + v.z*v.z + v.w*v.w;
    }
    __shared__ float rs[256], rss[256];
    rs[threadIdx.x] = s; rss[threadIdx.x] = ss;
    __syncthreads();
    for (int st = 128; st > 0; st >>= 1) {
        if (threadIdx.x < st) { rs[threadIdx.x] += rs[threadIdx.x+st]; rss[threadIdx.x] += rss[threadIdx.x+st]; }
        __syncthreads();
    }
    float mean = rs[0] * (1.f/32768.f);
    float var  = rss[0] * (1.f/32768.f) - mean*mean;
    float rstd = rsqrtf(var + EPS);

    float sc[8], sh[8];
    #pragma unroll
    for (int c = 0; c < 8; c++) {
        sc[c] = w[g*8+c] * rstd;
        sh[c] = bias[g*8+c] - mean * sc[c];
    }
    for (int it = 0; it < 16; it++) {
        int n = it * 256 + threadIdx.x;
        uint32_t hp[4], lp[4];
        #pragma unroll
        for (int p = 0; p < 4; p++) {
            float v0 = x[base + (size_t)(2*p  )*NTOK + n] * sc[2*p  ] + sh[2*p  ];
            float v1 = x[base + (size_t)(2*p+1)*NTOK + n] * sc[2*p+1] + sh[2*p+1];
            bf16 h0, l0, h1, l1;
            split2(v0, h0, l0); split2(v1, h1, l1);
            hp[p] = pk2(h0, h1); lp[p] = pk2(l0, l1);
        }
        size_t off = ((size_t)(b*NTOK + n)) * CHN + g*8;
        *(uint4*)(g_xnh + off) = make_uint4(hp[0], hp[1], hp[2], hp[3]);
        *(uint4*)(g_xnl + off) = make_uint4(lp[0], lp[1], lp[2], lp[3]);
    }
}

// ------------------------------------------------------------------
__global__ __launch_bounds__(256) void prep_w(const float* __restrict__ qkvw,
                                              const float* __restrict__ outw) {
    int idx = blockIdx.x * 256 + threadIdx.x;
    #pragma unroll
    for (int r = 0; r < 3; r++) {
        int i = idx + r * 65536;
        bf16 h, l; split2(qkvw[i], h, l);
        g_wqh[i] = h; g_wql[i] = l;
    }
    bf16 h, l; split2(outw[idx], h, l);
    g_woh[idx] = h; g_wol[idx] = l;
}

// ------------------------------------------------------------------
// split-bf16 HMMA GEMM: D[128 x 128] = sum over 3 segs of A[r][k] B[c][k]
// block 256 thr = 8 warps (4 m x 2 n); warp tile 32x64 (2x8 m16n8)
// MODE 0 = QKV, 1 = scores, 2 = AV, 3 = proj
// ------------------------------------------------------------------
template<int MODE>
__global__ __launch_bounds__(256, 2)
void tc_gemm(const float* __restrict__ bias,
             const float* __restrict__ resid,
             float* __restrict__ outf) {
    extern __shared__ char smem[];
    bf16* As = (bf16*)smem;                // [128][40]
    bf16* Bs = As + 128 * TPAD;            // [128][40]
    float* stg = (float*)smem;             // [128][132] (epilogue)
    const uint32_t sA = smem_u32(As);
    const uint32_t sB = smem_u32(Bs);

    const int tid  = threadIdx.x;
    const int lane = tid & 31;
    const int wid  = tid >> 5;
    const int warp_m = wid & 3;            // 32-row slab
    const int warp_n = wid >> 2;           // 64-col slab
    const int b = blockIdx.z;

    const bf16 *Ah, *Al, *Bh, *Bl;
    int lda, ldb;
    int n0 = 0, m0 = 0, c0 = 0;
    if (MODE == 0) {
        n0 = blockIdx.x * 128; m0 = blockIdx.y * 128;
        Ah = g_wqh + (size_t)m0 * CHN;  Al = g_wql + (size_t)m0 * CHN;
        Bh = g_xnh + ((size_t)(b*NTOK + n0)) * CHN;
        Bl = g_xnl + ((size_t)(b*NTOK + n0)) * CHN;
        lda = CHN; ldb = CHN;
    } else if (MODE == 1) {
        m0 = blockIdx.x * 128; n0 = blockIdx.y * 128;
        Ah = g_qh + ((size_t)(b*NTOK + n0)) * CHN;
        Al = g_ql + ((size_t)(b*NTOK + n0)) * CHN;
        Bh = g_kh + ((size_t)(b*NTOK + m0)) * CHN;
        Bl = g_kl + ((size_t)(b*NTOK + m0)) * CHN;
        lda = CHN; ldb = CHN;
    } else if (MODE == 2) {
        c0 = blockIdx.x * 128; n0 = blockIdx.y * 128;
        Ah = g_ph + ((size_t)b*NTOK + n0) * NTOK;
        Al = g_pl + ((size_t)b*NTOK + n0) * NTOK;
        Bh = g_vh + ((size_t)(b*CHN + c0)) * NTOK;
        Bl = g_vl + ((size_t)(b*CHN + c0)) * NTOK;
        lda = NTOK; ldb = NTOK;
    } else {
        n0 = blockIdx.x * 128; m0 = blockIdx.y * 128;
        Ah = g_woh + (size_t)m0 * CHN;  Al = g_wol + (size_t)m0 * CHN;
        Bh = g_aoh + ((size_t)(b*NTOK + n0)) * CHN;
        Bl = g_aol + ((size_t)(b*NTOK + n0)) * CHN;
        lda = CHN; ldb = CHN;
    }
    const int Ktot = (MODE == 2) ? NTOK : CHN;
    const int ncs  = Ktot / 32;
    const int total = 3 * ncs;

    float acc[2][8][4];
    #pragma unroll
    for (int i = 0; i < 2; i++)
        #pragma unroll
        for (int j = 0; j < 8; j++)
            #pragma unroll
            for (int q = 0; q < 4; q++) acc[i][j][q] = 0.f;

    // per-thread gmem load map: 128x32 bf16 per tile -> 2 x uint4 per thread
    const int lrow0 = tid >> 2;          // 0..63  (+64 second)
    const int lcol  = (tid & 3) * 8;     // 0,8,16,24

    uint4 ra[2], rb[2];
    auto load_chunk = [&](int cc) {
        int seg = cc / ncs, r = cc - seg * ncs;
        int kk = r * 32;
        const bf16* Ap = (seg == 1) ? Al : Ah;
        const bf16* Bp = (seg == 2) ? Bl : Bh;
        #pragma unroll
        for (int i = 0; i < 2; i++) {
            int row = lrow0 + i * 64;
            ra[i] = *(const uint4*)(Ap + (size_t)row * lda + kk + lcol);
            rb[i] = *(const uint4*)(Bp + (size_t)row * ldb + kk + lcol);
        }
    };

    load_chunk(0);
    for (int cc = 0; cc < total; cc++) {
        __syncthreads();
        #pragma unroll
        for (int i = 0; i < 2; i++) {
            int row = lrow0 + i * 64;
            *(uint4*)(As + row * TPAD + lcol) = ra[i];
            *(uint4*)(Bs + row * TPAD + lcol) = rb[i];
        }
        __syncthreads();
        if (cc + 1 < total) load_chunk(cc + 1);

        #pragma unroll
        for (int ks = 0; ks < 2; ks++) {
            uint32_t a[2][4];
            #pragma unroll
            for (int mi = 0; mi < 2; mi++) {
                uint32_t addr = sA + ((warp_m*32 + mi*16 + (lane & 15)) * TPAD
                                      + ks*16 + (lane >> 4) * 8) * 2;
                ldsm_x4(a[mi][0], a[mi][1], a[mi][2], a[mi][3], addr);
            }
            #pragma unroll
            for (int ni = 0; ni < 4; ni++) {
                uint32_t b0, b1, b2, b3;
                uint32_t addr = sB + ((warp_n*64 + ni*16 + (lane & 15)) * TPAD
                                      + ks*16 + (lane >> 4) * 8) * 2;
                ldsm_x4(b0, b1, b2, b3, addr);
                #pragma unroll
                for (int mi = 0; mi < 2; mi++) {
                    mma_bf16(acc[mi][2*ni],   a[mi][0], a[mi][1], a[mi][2], a[mi][3], b0, b2);
                    mma_bf16(acc[mi][2*ni+1], a[mi][0], a[mi][1], a[mi][2], a[mi][3], b1, b3);
                }
            }
        }
    }
    __syncthreads();   // tiles dead; smem becomes stg

    // ---- stage accumulators to smem fp32 [128][132] ----
    #pragma unroll
    for (int mi = 0; mi < 2; mi++) {
        #pragma unroll
        for (int nj = 0; nj < 8; nj++) {
            int r = warp_m*32 + mi*16 + (lane >> 2);
            int c = warp_n*64 + nj*8 + (lane & 3) * 2;
            *(float2*)&stg[r * SPAD + c]       = make_float2(acc[mi][nj][0], acc[mi][nj][1]);
            *(float2*)&stg[(r + 8) * SPAD + c] = make_float2(acc[mi][nj][2], acc[mi][nj][3]);
        }
    }
    __syncthreads();

    // ---- writeback ----
    const int r = tid >> 1;
    const int cb = (tid & 1) * 64;
    if (MODE == 1) {
        float* Srow = g_attn + (size_t)b*NTOK*NTOK + (size_t)(n0 + r)*NTOK + m0 + cb;
        #pragma unroll
        for (int j = 0; j < 64; j += 4) {
            float4 o = make_float4(stg[r*SPAD + cb + j]     * 0.0625f,
                                   stg[r*SPAD + cb + j + 1] * 0.0625f,
                                   stg[r*SPAD + cb + j + 2] * 0.0625f,
                                   stg[r*SPAD + cb + j + 3] * 0.0625f);
            *(float4*)(Srow + j) = o;
        }
    } else if (MODE == 2) {
        bf16* Hr = g_aoh + ((size_t)(b*NTOK + n0 + r)) * CHN + c0 + cb;
        bf16* Lr = g_aol + ((size_t)(b*NTOK + n0 + r)) * CHN + c0 + cb;
        #pragma unroll
        for (int j0 = 0; j0 < 64; j0 += 8) {
            uint32_t h4[4], l4[4];
            #pragma unroll
            for (int p = 0; p < 4; p++) {
                float v0 = stg[r*SPAD + cb + j0 + 2*p];
                float v1 = stg[r*SPAD + cb + j0 + 2*p + 1];
                bf16 h0,l0,h1,l1; split2(v0,h0,l0); split2(v1,h1,l1);
                h4[p] = pk2(h0,h1); l4[p] = pk2(l0,l1);
            }
            *(uint4*)(Hr + j0) = make_uint4(h4[0],h4[1],h4[2],h4[3]);
            *(uint4*)(Lr + j0) = make_uint4(l4[0],l4[1],l4[2],l4[3]);
        }
    } else if (MODE == 3) {
        size_t roff = ((size_t)(b*CHN + m0 + r)) * NTOK + n0 + cb;
        float bb = bias[m0 + r];
        #pragma unroll
        for (int j = 0; j < 64; j += 4) {
            float4 rr = *(const float4*)(resid + roff + j);
            float4 o = make_float4(stg[r*SPAD + cb + j]     + bb + rr.x,
                                   stg[r*SPAD + cb + j + 1] + bb + rr.y,
                                   stg[r*SPAD + cb + j + 2] + bb + rr.z,
                                   stg[r*SPAD + cb + j + 3] + bb + rr.w);
            *(float4*)(outf + roff + j) = o;
        }
    } else {  // MODE 0
        if (m0 >= 512) {   // V rows: [c][m] split + bias
            float bb = bias[m0 + r];
            bf16* Hr = g_vh + ((size_t)(b*CHN + m0 - 512 + r)) * NTOK + n0 + cb;
            bf16* Lr = g_vl + ((size_t)(b*CHN + m0 - 512 + r)) * NTOK + n0 + cb;
            #pragma unroll
            for (int j0 = 0; j0 < 64; j0 += 8) {
                uint32_t h4[4], l4[4];
                #pragma unroll
                for (int p = 0; p < 4; p++) {
                    float v0 = stg[r*SPAD + cb + j0 + 2*p]     + bb;
                    float v1 = stg[r*SPAD + cb + j0 + 2*p + 1] + bb;
                    bf16 h0,l0,h1,l1; split2(v0,h0,l0); split2(v1,h1,l1);
                    h4[p] = pk2(h0,h1); l4[p] = pk2(l0,l1);
                }
                *(uint4*)(Hr + j0) = make_uint4(h4[0],h4[1],h4[2],h4[3]);
                *(uint4*)(Lr + j0) = make_uint4(l4[0],l4[1],l4[2],l4[3]);
            }
        } else {           // Q/K rows: transpose to [n][c] split + bias
            bf16* dsth = ((m0 < 256) ? g_qh : g_kh) + ((size_t)b*NTOK) * CHN;
            bf16* dstl = ((m0 < 256) ? g_ql : g_kl) + ((size_t)b*NTOK) * CHN;
            int obase = m0 & 255;
            #pragma unroll
            for (int it = 0; it < 8; it++) {
                int lin = tid + it * 256;
                int j  = lin >> 4;      // token col 0..127
                int ck = lin & 15;      // 8-channel chunk
                uint32_t h4[4], l4[4];
                #pragma unroll
                for (int p = 0; p < 4; p++) {
                    float v0 = stg[(ck*8 + 2*p    ) * SPAD + j] + bias[m0 + ck*8 + 2*p];
                    float v1 = stg[(ck*8 + 2*p + 1) * SPAD + j] + bias[m0 + ck*8 + 2*p + 1];
                    bf16 h0,l0,h1,l1; split2(v0,h0,l0); split2(v1,h1,l1);
                    h4[p] = pk2(h0,h1); l4[p] = pk2(l0,l1);
                }
                size_t off = ((size_t)(n0 + j)) * CHN + obase + ck*8;
                *(uint4*)(dsth + off) = make_uint4(h4[0],h4[1],h4[2],h4[3]);
                *(uint4*)(dstl + off) = make_uint4(l4[0],l4[1],l4[2],l4[3]);
            }
        }
    }
}

// ------------------------------------------------------------------
// softmax: fp32 scores row -> split bf16 probs
// ------------------------------------------------------------------
__global__ __launch_bounds__(256) void softmax_kernel() {
    size_t row = blockIdx.x;
    const float4* pv = (const float4*)(g_attn + row * NTOK);
    uint2* ph = (uint2*)(g_ph + row * NTOK);
    uint2* pl = (uint2*)(g_pl + row * NTOK);
    const int t = threadIdx.x;
    float4 v[4];
    float mx = -1e30f;
    #pragma unroll
    for (int i = 0; i < 4; i++) {
        v[i] = pv[t + i*256];
        mx = fmaxf(mx, fmaxf(fmaxf(v[i].x, v[i].y), fmaxf(v[i].z, v[i].w)));
    }
    __shared__ float red[256];
    red[t] = mx; __syncthreads();
    for (int st = 128; st > 0; st >>= 1) {
        if (t < st) red[t] = fmaxf(red[t], red[t+st]);
        __syncthreads();
    }
    mx = red[0];
    __syncthreads();
    float s = 0.f;
    #pragma unroll
    for (int i = 0; i < 4; i++) {
        v[i].x = __expf(v[i].x - mx); v[i].y = __expf(v[i].y - mx);
        v[i].z = __expf(v[i].z - mx); v[i].w = __expf(v[i].w - mx);
        s += v[i].x + v[i].y + v[i].z + v[i].w;
    }
    red[t] = s; __syncthreads();
    for (int st = 128; st > 0; st >>= 1) {
        if (t < st) red[t] += red[t+st];
        __syncthreads();
    }
    float inv = 1.f / red[0];
    #pragma unroll
    for (int i = 0; i < 4; i++) {
        float a0 = v[i].x*inv, a1 = v[i].y*inv, a2 = v[i].z*inv, a3 = v[i].w*inv;
        bf16 h0,l0,h1,l1,h2,l2,h3,l3;
        split2(a0,h0,l0); split2(a1,h1,l1); split2(a2,h2,l2); split2(a3,h3,l3);
        ph[t + i*256] = make_uint2(pk2(h0,h1), pk2(h2,h3));
        pl[t + i*256] = make_uint2(pk2(l0,l1), pk2(l2,l3));
    }
}

// ------------------------------------------------------------------
extern "C" void kernel_launch(void* const* d_in, const int* in_sizes, int n_in,
                              void* d_out, int out_size) {
    const float* x    = (const float*)d_in[0];
    const float* gnw  = (const float*)d_in[1];
    const float* gnb  = (const float*)d_in[2];
    const float* qkvw = (const float*)d_in[3];
    const float* qkvb = (const float*)d_in[4];
    const float* ow   = (const float*)d_in[5];
    const float* ob   = (const float*)d_in[6];
    float* y = (float*)d_out;

    cudaFuncSetAttribute(tc_gemm<0>, cudaFuncAttributeMaxDynamicSharedMemorySize, SMEM_BYTES);
    cudaFuncSetAttribute(tc_gemm<1>, cudaFuncAttributeMaxDynamicSharedMemorySize, SMEM_BYTES);
    cudaFuncSetAttribute(tc_gemm<2>, cudaFuncAttributeMaxDynamicSharedMemorySize, SMEM_BYTES);
    cudaFuncSetAttribute(tc_gemm<3>, cudaFuncAttributeMaxDynamicSharedMemorySize, SMEM_BYTES);

    prep_w   <<<256, 256>>>(qkvw, ow);
    gn_kernel<<<BATCH*32, 256>>>(x, gnw, gnb);
    tc_gemm<0><<<dim3(NTOK/128, 6, BATCH), 256, SMEM_BYTES>>>(qkvb, nullptr, nullptr);
    tc_gemm<1><<<dim3(NTOK/128, NTOK/128, BATCH), 256, SMEM_BYTES>>>(nullptr, nullptr, nullptr);
    softmax_kernel<<<BATCH*NTOK, 256>>>();
    tc_gemm<2><<<dim3(CHN/128, NTOK/128, BATCH), 256, SMEM_BYTES>>>(nullptr, nullptr, nullptr);
    tc_gemm<3><<<dim3(NTOK/128, CHN/128, BATCH), 256, SMEM_BYTES>>>(ob, x, y);
}

// round 4
// speedup vs baseline: 2.0615x; 1.0496x over previous
#include <cuda_runtime.h>
#include <cuda_bf16.h>
#include <cstdint>

#define BATCH 4
#define CHN   256
#define NTOK  4096
#define EPS   1e-5f

typedef __nv_bfloat16 bf16;

// ------------------------------------------------------------------
// scratch (__device__ globals; no allocations allowed)
// ------------------------------------------------------------------
__device__ bf16 g_xnh[(size_t)BATCH*NTOK*CHN];   // groupnormed x hi [b][n][c]
__device__ bf16 g_xnl[(size_t)BATCH*NTOK*CHN];
__device__ bf16 g_qh [(size_t)BATCH*NTOK*CHN];   // Q split [b][n][c]
__device__ bf16 g_ql [(size_t)BATCH*NTOK*CHN];
__device__ bf16 g_kh [(size_t)BATCH*NTOK*CHN];   // K split [b][m][c]
__device__ bf16 g_kl [(size_t)BATCH*NTOK*CHN];
__device__ bf16 g_vh [(size_t)BATCH*CHN*NTOK];   // V split [b][c][m]
__device__ bf16 g_vl [(size_t)BATCH*CHN*NTOK];
__device__ float g_attn[(size_t)BATCH*NTOK*NTOK];// scores fp32 [b][n][m]
__device__ bf16 g_ph[(size_t)BATCH*NTOK*NTOK];   // probs split [b][n][m]
__device__ bf16 g_pl[(size_t)BATCH*NTOK*NTOK];
__device__ bf16 g_aoh[(size_t)BATCH*NTOK*CHN];   // attn-out split [b][n][c]
__device__ bf16 g_aol[(size_t)BATCH*NTOK*CHN];
__device__ bf16 g_wqh[3*CHN*CHN], g_wql[3*CHN*CHN];
__device__ bf16 g_woh[CHN*CHN],   g_wol[CHN*CHN];

// ------------------------------------------------------------------
__device__ __forceinline__ uint32_t smem_u32(const void* p) {
    uint32_t a;
    asm("{ .reg .u64 t; cvta.to.shared.u64 t, %1; cvt.u32.u64 %0, t; }" : "=r"(a) : "l"(p));
    return a;
}
__device__ __forceinline__ void ldsm_x4(uint32_t& r0, uint32_t& r1, uint32_t& r2,
                                        uint32_t& r3, uint32_t addr) {
    asm volatile("ldmatrix.sync.aligned.m8n8.x4.shared.b16 {%0,%1,%2,%3}, [%4];"
                 : "=r"(r0), "=r"(r1), "=r"(r2), "=r"(r3) : "r"(addr));
}
__device__ __forceinline__ void mma_bf16(float* c, uint32_t a0, uint32_t a1,
                                         uint32_t a2, uint32_t a3,
                                         uint32_t b0, uint32_t b1) {
    asm volatile("mma.sync.aligned.m16n8k16.row.col.f32.bf16.bf16.f32 "
                 "{%0,%1,%2,%3}, {%4,%5,%6,%7}, {%8,%9}, {%0,%1,%2,%3};"
                 : "+f"(c[0]), "+f"(c[1]), "+f"(c[2]), "+f"(c[3])
                 : "r"(a0), "r"(a1), "r"(a2), "r"(a3), "r"(b0), "r"(b1));
}
__device__ __forceinline__ void cpasync16(uint32_t dst, const void* src) {
    asm volatile("cp.async.cg.shared.global [%0], [%1], 16;" :: "r"(dst), "l"(src));
}
#define CP_COMMIT() asm volatile("cp.async.commit_group;" ::: "memory")
#define CP_WAIT1()  asm volatile("cp.async.wait_group 1;" ::: "memory")
#define CP_WAIT0()  asm volatile("cp.async.wait_group 0;" ::: "memory")

__device__ __forceinline__ uint32_t pk2(bf16 a, bf16 b) {
    __nv_bfloat162 t; t.x = a; t.y = b;
    return *reinterpret_cast<uint32_t*>(&t);
}
__device__ __forceinline__ void split2(float v, bf16& h, bf16& l) {
    h = __float2bfloat16(v);
    l = __float2bfloat16(v - __bfloat162float(h));
}

// SMEM: 2 stages x (A[128][40] + B[128][40]) bf16 = 40960 B, union with
// epilogue stg fp32 [128][132] = 67584 B
#define TPAD 40
#define SPAD 132
#define STAGE_BYTES 20480
#define SMEM_BYTES  (128 * SPAD * 4)   // 67584

// ------------------------------------------------------------------
// GroupNorm -> split bf16 token-major [b][n][c]
// ------------------------------------------------------------------
__global__ __launch_bounds__(256) void gn_kernel(const float* __restrict__ x,
                                                 const float* __restrict__ w,
                                                 const float* __restrict__ bias) {
    int b = blockIdx.x >> 5;
    int g = blockIdx.x & 31;
    size_t base = ((size_t)b * CHN + g * 8) * NTOK;
    const float4* xv = (const float4*)(x + base);
    const int NV = 8 * NTOK / 4;

    float s = 0.f, ss = 0.f;
    for (int i = threadIdx.x; i < NV; i += 256) {
        float4 v = xv[i];
        s  += v.x + v.y + v.z + v.w;
        ss += v.x*v.x + v.y*v.y + v.z*v.z + v.w*v.w;
    }
    __shared__ float rs[256], rss[256];
    rs[threadIdx.x] = s; rss[threadIdx.x] = ss;
    __syncthreads();
    for (int st = 128; st > 0; st >>= 1) {
        if (threadIdx.x < st) { rs[threadIdx.x] += rs[threadIdx.x+st]; rss[threadIdx.x] += rss[threadIdx.x+st]; }
        __syncthreads();
    }
    float mean = rs[0] * (1.f/32768.f);
    float var  = rss[0] * (1.f/32768.f) - mean*mean;
    float rstd = rsqrtf(var + EPS);

    float sc[8], sh[8];
    #pragma unroll
    for (int c = 0; c < 8; c++) {
        sc[c] = w[g*8+c] * rstd;
        sh[c] = bias[g*8+c] - mean * sc[c];
    }
    for (int it = 0; it < 16; it++) {
        int n = it * 256 + threadIdx.x;
        uint32_t hp[4], lp[4];
        #pragma unroll
        for (int p = 0; p < 4; p++) {
            float v0 = x[base + (size_t)(2*p  )*NTOK + n] * sc[2*p  ] + sh[2*p  ];
            float v1 = x[base + (size_t)(2*p+1)*NTOK + n] * sc[2*p+1] + sh[2*p+1];
            bf16 h0, l0, h1, l1;
            split2(v0, h0, l0); split2(v1, h1, l1);
            hp[p] = pk2(h0, h1); lp[p] = pk2(l0, l1);
        }
        size_t off = ((size_t)(b*NTOK + n)) * CHN + g*8;
        *(uint4*)(g_xnh + off) = make_uint4(hp[0], hp[1], hp[2], hp[3]);
        *(uint4*)(g_xnl + off) = make_uint4(lp[0], lp[1], lp[2], lp[3]);
    }
}

// ------------------------------------------------------------------
__global__ __launch_bounds__(256) void prep_w(const float* __restrict__ qkvw,
                                              const float* __restrict__ outw) {
    int idx = blockIdx.x * 256 + threadIdx.x;
    #pragma unroll
    for (int r = 0; r < 3; r++) {
        int i = idx + r * 65536;
        bf16 h, l; split2(qkvw[i], h, l);
        g_wqh[i] = h; g_wql[i] = l;
    }
    bf16 h, l; split2(outw[idx], h, l);
    g_woh[idx] = h; g_wol[idx] = l;
}

// ------------------------------------------------------------------
// split-bf16 HMMA GEMM: D[128 x 128] = sum over 3 segs of A[r][k] B[c][k]
// 128 threads = 4 warps (2 m x 2 n); warp tile 64x64 (4x8 m16n8)
// cp.async 2-stage double buffer, K-chunk 32
// MODE 0 = QKV, 1 = scores, 2 = AV, 3 = proj
// ------------------------------------------------------------------
template<int MODE>
__global__ __launch_bounds__(128)
void tc_gemm(const float* __restrict__ bias,
             const float* __restrict__ resid,
             float* __restrict__ outf) {
    extern __shared__ char smem[];
    float* stg = (float*)smem;             // [128][132] (epilogue)
    const uint32_t sbase = smem_u32(smem);

    const int tid  = threadIdx.x;
    const int lane = tid & 31;
    const int wid  = tid >> 5;
    const int warp_m = wid & 1;            // 64-row slab
    const int warp_n = wid >> 1;           // 64-col slab
    const int b = blockIdx.z;

    const bf16 *Ah, *Al, *Bh, *Bl;
    int lda, ldb;
    int n0 = 0, m0 = 0, c0 = 0;
    if (MODE == 0) {
        n0 = blockIdx.x * 128; m0 = blockIdx.y * 128;
        Ah = g_wqh + (size_t)m0 * CHN;  Al = g_wql + (size_t)m0 * CHN;
        Bh = g_xnh + ((size_t)(b*NTOK + n0)) * CHN;
        Bl = g_xnl + ((size_t)(b*NTOK + n0)) * CHN;
        lda = CHN; ldb = CHN;
    } else if (MODE == 1) {
        m0 = blockIdx.x * 128; n0 = blockIdx.y * 128;
        Ah = g_qh + ((size_t)(b*NTOK + n0)) * CHN;
        Al = g_ql + ((size_t)(b*NTOK + n0)) * CHN;
        Bh = g_kh + ((size_t)(b*NTOK + m0)) * CHN;
        Bl = g_kl + ((size_t)(b*NTOK + m0)) * CHN;
        lda = CHN; ldb = CHN;
    } else if (MODE == 2) {
        c0 = blockIdx.x * 128; n0 = blockIdx.y * 128;
        Ah = g_ph + ((size_t)b*NTOK + n0) * NTOK;
        Al = g_pl + ((size_t)b*NTOK + n0) * NTOK;
        Bh = g_vh + ((size_t)(b*CHN + c0)) * NTOK;
        Bl = g_vl + ((size_t)(b*CHN + c0)) * NTOK;
        lda = NTOK; ldb = NTOK;
    } else {
        n0 = blockIdx.x * 128; m0 = blockIdx.y * 128;
        Ah = g_woh + (size_t)m0 * CHN;  Al = g_wol + (size_t)m0 * CHN;
        Bh = g_aoh + ((size_t)(b*NTOK + n0)) * CHN;
        Bl = g_aol + ((size_t)(b*NTOK + n0)) * CHN;
        lda = CHN; ldb = CHN;
    }
    const int Ktot = (MODE == 2) ? NTOK : CHN;
    const int ncs  = Ktot / 32;
    const int total = 3 * ncs;

    float acc[4][8][4];
    #pragma unroll
    for (int i = 0; i < 4; i++)
        #pragma unroll
        for (int j = 0; j < 8; j++)
            #pragma unroll
            for (int q = 0; q < 4; q++) acc[i][j][q] = 0.f;

    // cp.async map: per tile 128 rows x 32 cols bf16 = 128x64B; 4 rows/iter-group
    const int prow = tid >> 2;           // 0..31 (+32*i)
    const int pcol = (tid & 3) * 8;      // bf16 col: 0,8,16,24

    auto prefetch = [&](int cc, int s) {
        if (cc >= total) return;
        int seg = cc / ncs, rch = cc - seg * ncs;
        int kk = rch * 32;
        const bf16* Ap = (seg == 1) ? Al : Ah;
        const bf16* Bp = (seg == 2) ? Bl : Bh;
        uint32_t dA = sbase + s * STAGE_BYTES;
        uint32_t dB = dA + 10240;
        #pragma unroll
        for (int i = 0; i < 4; i++) {
            int row = prow + 32 * i;
            cpasync16(dA + (row * TPAD + pcol) * 2, Ap + (size_t)row * lda + kk + pcol);
            cpasync16(dB + (row * TPAD + pcol) * 2, Bp + (size_t)row * ldb + kk + pcol);
        }
    };

    prefetch(0, 0); CP_COMMIT();
    prefetch(1, 1); CP_COMMIT();

    for (int cc = 0; cc < total; cc++) {
        const int s = cc & 1;
        CP_WAIT1();
        __syncthreads();
        const uint32_t tA = sbase + s * STAGE_BYTES;
        const uint32_t tB = tA + 10240;
        #pragma unroll
        for (int ks = 0; ks < 2; ks++) {
            uint32_t a[4][4];
            #pragma unroll
            for (int mi = 0; mi < 4; mi++) {
                uint32_t addr = tA + ((warp_m*64 + mi*16 + (lane & 15)) * TPAD
                                      + ks*16 + (lane >> 4) * 8) * 2;
                ldsm_x4(a[mi][0], a[mi][1], a[mi][2], a[mi][3], addr);
            }
            #pragma unroll
            for (int ni = 0; ni < 4; ni++) {
                uint32_t b0, b1, b2, b3;
                uint32_t addr = tB + ((warp_n*64 + ni*16 + (lane & 15)) * TPAD
                                      + ks*16 + (lane >> 4) * 8) * 2;
                ldsm_x4(b0, b1, b2, b3, addr);
                #pragma unroll
                for (int mi = 0; mi < 4; mi++) {
                    mma_bf16(acc[mi][2*ni],   a[mi][0], a[mi][1], a[mi][2], a[mi][3], b0, b2);
                    mma_bf16(acc[mi][2*ni+1], a[mi][0], a[mi][1], a[mi][2], a[mi][3], b1, b3);
                }
            }
        }
        __syncthreads();
        prefetch(cc + 2, s);
        CP_COMMIT();
    }
    CP_WAIT0();
    __syncthreads();   // tiles dead; smem becomes stg

    // ---- stage accumulators to smem fp32 [128][132] ----
    #pragma unroll
    for (int mi = 0; mi < 4; mi++) {
        #pragma unroll
        for (int nj = 0; nj < 8; nj++) {
            int r = warp_m*64 + mi*16 + (lane >> 2);
            int c = warp_n*64 + nj*8 + (lane & 3) * 2;
            *(float2*)&stg[r * SPAD + c]       = make_float2(acc[mi][nj][0], acc[mi][nj][1]);
            *(float2*)&stg[(r + 8) * SPAD + c] = make_float2(acc[mi][nj][2], acc[mi][nj][3]);
        }
    }
    __syncthreads();

    // ---- writeback (128 threads; thread tid owns row tid, all 128 cols) ----
    const int r = tid;
    if (MODE == 1) {
        float* Srow = g_attn + (size_t)b*NTOK*NTOK + (size_t)(n0 + r)*NTOK + m0;
        #pragma unroll
        for (int j = 0; j < 128; j += 4) {
            float4 o = make_float4(stg[r*SPAD + j]     * 0.0625f,
                                   stg[r*SPAD + j + 1] * 0.0625f,
                                   stg[r*SPAD + j + 2] * 0.0625f,
                                   stg[r*SPAD + j + 3] * 0.0625f);
            *(float4*)(Srow + j) = o;
        }
    } else if (MODE == 2) {
        bf16* Hr = g_aoh + ((size_t)(b*NTOK + n0 + r)) * CHN + c0;
        bf16* Lr = g_aol + ((size_t)(b*NTOK + n0 + r)) * CHN + c0;
        #pragma unroll
        for (int j0 = 0; j0 < 128; j0 += 8) {
            uint32_t h4[4], l4[4];
            #pragma unroll
            for (int p = 0; p < 4; p++) {
                float v0 = stg[r*SPAD + j0 + 2*p];
                float v1 = stg[r*SPAD + j0 + 2*p + 1];
                bf16 h0,l0,h1,l1; split2(v0,h0,l0); split2(v1,h1,l1);
                h4[p] = pk2(h0,h1); l4[p] = pk2(l0,l1);
            }
            *(uint4*)(Hr + j0) = make_uint4(h4[0],h4[1],h4[2],h4[3]);
            *(uint4*)(Lr + j0) = make_uint4(l4[0],l4[1],l4[2],l4[3]);
        }
    } else if (MODE == 3) {
        size_t roff = ((size_t)(b*CHN + m0 + r)) * NTOK + n0;
        float bb = bias[m0 + r];
        #pragma unroll
        for (int j = 0; j < 128; j += 4) {
            float4 rr = *(const float4*)(resid + roff + j);
            float4 o = make_float4(stg[r*SPAD + j]     + bb + rr.x,
                                   stg[r*SPAD + j + 1] + bb + rr.y,
                                   stg[r*SPAD + j + 2] + bb + rr.z,
                                   stg[r*SPAD + j + 3] + bb + rr.w);
            *(float4*)(outf + roff + j) = o;
        }
    } else {  // MODE 0
        if (m0 >= 512) {   // V rows: [c][m] split + bias
            float bb = bias[m0 + r];
            bf16* Hr = g_vh + ((size_t)(b*CHN + m0 - 512 + r)) * NTOK + n0;
            bf16* Lr = g_vl + ((size_t)(b*CHN + m0 - 512 + r)) * NTOK + n0;
            #pragma unroll
            for (int j0 = 0; j0 < 128; j0 += 8) {
                uint32_t h4[4], l4[4];
                #pragma unroll
                for (int p = 0; p < 4; p++) {
                    float v0 = stg[r*SPAD + j0 + 2*p]     + bb;
                    float v1 = stg[r*SPAD + j0 + 2*p + 1] + bb;
                    bf16 h0,l0,h1,l1; split2(v0,h0,l0); split2(v1,h1,l1);
                    h4[p] = pk2(h0,h1); l4[p] = pk2(l0,l1);
                }
                *(uint4*)(Hr + j0) = make_uint4(h4[0],h4[1],h4[2],h4[3]);
                *(uint4*)(Lr + j0) = make_uint4(l4[0],l4[1],l4[2],l4[3]);
            }
        } else {           // Q/K rows: transpose to [n][c] split + bias
            bf16* dsth = ((m0 < 256) ? g_qh : g_kh) + ((size_t)b*NTOK) * CHN;
            bf16* dstl = ((m0 < 256) ? g_ql : g_kl) + ((size_t)b*NTOK) * CHN;
            int obase = m0 & 255;
            #pragma unroll
            for (int it = 0; it < 16; it++) {
                int lin = tid + it * 128;
                int j  = lin >> 4;      // token col 0..127
                int ck = lin & 15;      // 8-channel chunk
                uint32_t h4[4], l4[4];
                #pragma unroll
                for (int p = 0; p < 4; p++) {
                    float v0 = stg[(ck*8 + 2*p    ) * SPAD + j] + bias[m0 + ck*8 + 2*p];
                    float v1 = stg[(ck*8 + 2*p + 1) * SPAD + j] + bias[m0 + ck*8 + 2*p + 1];
                    bf16 h0,l0,h1,l1; split2(v0,h0,l0); split2(v1,h1,l1);
                    h4[p] = pk2(h0,h1); l4[p] = pk2(l0,l1);
                }
                size_t off = ((size_t)(n0 + j)) * CHN + obase + ck*8;
                *(uint4*)(dsth + off) = make_uint4(h4[0],h4[1],h4[2],h4[3]);
                *(uint4*)(dstl + off) = make_uint4(l4[0],l4[1],l4[2],l4[3]);
            }
        }
    }
}

// ------------------------------------------------------------------
// softmax: fp32 scores row -> split bf16 probs
// ------------------------------------------------------------------
__global__ __launch_bounds__(256) void softmax_kernel() {
    size_t row = blockIdx.x;
    const float4* pv = (const float4*)(g_attn + row * NTOK);
    uint2* ph = (uint2*)(g_ph + row * NTOK);
    uint2* pl = (uint2*)(g_pl + row * NTOK);
    const int t = threadIdx.x;
    float4 v[4];
    float mx = -1e30f;
    #pragma unroll
    for (int i = 0; i < 4; i++) {
        v[i] = pv[t + i*256];
        mx = fmaxf(mx, fmaxf(fmaxf(v[i].x, v[i].y), fmaxf(v[i].z, v[i].w)));
    }
    __shared__ float red[256];
    red[t] = mx; __syncthreads();
    for (int st = 128; st > 0; st >>= 1) {
        if (t < st) red[t] = fmaxf(red[t], red[t+st]);
        __syncthreads();
    }
    mx = red[0];
    __syncthreads();
    float s = 0.f;
    #pragma unroll
    for (int i = 0; i < 4; i++) {
        v[i].x = __expf(v[i].x - mx); v[i].y = __expf(v[i].y - mx);
        v[i].z = __expf(v[i].z - mx); v[i].w = __expf(v[i].w - mx);
        s += v[i].x + v[i].y + v[i].z + v[i].w;
    }
    red[t] = s; __syncthreads();
    for (int st = 128; st > 0; st >>= 1) {
        if (t < st) red[t] += red[t+st];
        __syncthreads();
    }
    float inv = 1.f / red[0];
    #pragma unroll
    for (int i = 0; i < 4; i++) {
        float a0 = v[i].x*inv, a1 = v[i].y*inv, a2 = v[i].z*inv, a3 = v[i].w*inv;
        bf16 h0,l0,h1,l1,h2,l2,h3,l3;
        split2(a0,h0,l0); split2(a1,h1,l1); split2(a2,h2,l2); split2(a3,h3,l3);
        ph[t + i*256] = make_uint2(pk2(h0,h1), pk2(h2,h3));
        pl[t + i*256] = make_uint2(pk2(l0,l1), pk2(l2,l3));
    }
}

// ------------------------------------------------------------------
extern "C" void kernel_launch(void* const* d_in, const int* in_sizes, int n_in,
                              void* d_out, int out_size) {
    const float* x    = (const float*)d_in[0];
    const float* gnw  = (const float*)d_in[1];
    const float* gnb  = (const float*)d_in[2];
    const float* qkvw = (const float*)d_in[3];
    const float* qkvb = (const float*)d_in[4];
    const float* ow   = (const float*)d_in[5];
    const float* ob   = (const float*)d_in[6];
    float* y = (float*)d_out;

    cudaFuncSetAttribute(tc_gemm<0>, cudaFuncAttributeMaxDynamicSharedMemorySize, SMEM_BYTES);
    cudaFuncSetAttribute(tc_gemm<1>, cudaFuncAttributeMaxDynamicSharedMemorySize, SMEM_BYTES);
    cudaFuncSetAttribute(tc_gemm<2>, cudaFuncAttributeMaxDynamicSharedMemorySize, SMEM_BYTES);
    cudaFuncSetAttribute(tc_gemm<3>, cudaFuncAttributeMaxDynamicSharedMemorySize, SMEM_BYTES);

    prep_w   <<<256, 256>>>(qkvw, ow);
    gn_kernel<<<BATCH*32, 256>>>(x, gnw, gnb);
    tc_gemm<0><<<dim3(NTOK/128, 6, BATCH), 128, SMEM_BYTES>>>(qkvb, nullptr, nullptr);
    tc_gemm<1><<<dim3(NTOK/128, NTOK/128, BATCH), 128, SMEM_BYTES>>>(nullptr, nullptr, nullptr);
    softmax_kernel<<<BATCH*NTOK, 256>>>();
    tc_gemm<2><<<dim3(CHN/128, NTOK/128, BATCH), 128, SMEM_BYTES>>>(nullptr, nullptr, nullptr);
    tc_gemm<3><<<dim3(NTOK/128, CHN/128, BATCH), 128, SMEM_BYTES>>>(ob, x, y);
}

// round 5
// speedup vs baseline: 2.9448x; 1.4284x over previous
#include <cuda_runtime.h>
#include <cuda_fp16.h>
#include <cstdint>

#define BATCH 4
#define CHN   256
#define NTOK  4096
#define EPS   1e-5f

typedef __half h16;

// ------------------------------------------------------------------
// scratch (__device__ globals; no allocations allowed)
// A-side operands keep hi+lo; B-side operands hi only.
// ------------------------------------------------------------------
__device__ h16 g_xnh[(size_t)BATCH*NTOK*CHN];    // xn hi [b][n][c]   (B in QKV)
__device__ h16 g_qh [(size_t)BATCH*NTOK*CHN];    // Q hi/lo [b][n][c] (A in scores)
__device__ h16 g_ql [(size_t)BATCH*NTOK*CHN];
__device__ h16 g_kh [(size_t)BATCH*NTOK*CHN];    // K hi [b][m][c]    (B in scores)
__device__ h16 g_vh [(size_t)BATCH*CHN*NTOK];    // V hi [b][c][m]    (B in AV)
__device__ float g_attn[(size_t)BATCH*NTOK*NTOK];// scores fp32 [b][n][m]
__device__ h16 g_ph[(size_t)BATCH*NTOK*NTOK];    // probs hi/lo [b][n][m] (A in AV)
__device__ h16 g_pl[(size_t)BATCH*NTOK*NTOK];
__device__ h16 g_aoh[(size_t)BATCH*NTOK*CHN];    // attn-out hi [b][n][c] (B in proj)
__device__ h16 g_wqh[3*CHN*CHN], g_wql[3*CHN*CHN]; // A in QKV
__device__ h16 g_woh[CHN*CHN],   g_wol[CHN*CHN];   // A in proj

// ------------------------------------------------------------------
__device__ __forceinline__ uint32_t smem_u32(const void* p) {
    uint32_t a;
    asm("{ .reg .u64 t; cvta.to.shared.u64 t, %1; cvt.u32.u64 %0, t; }" : "=r"(a) : "l"(p));
    return a;
}
__device__ __forceinline__ void ldsm_x4(uint32_t& r0, uint32_t& r1, uint32_t& r2,
                                        uint32_t& r3, uint32_t addr) {
    asm volatile("ldmatrix.sync.aligned.m8n8.x4.shared.b16 {%0,%1,%2,%3}, [%4];"
                 : "=r"(r0), "=r"(r1), "=r"(r2), "=r"(r3) : "r"(addr));
}
__device__ __forceinline__ void mma_f16(float* c, uint32_t a0, uint32_t a1,
                                        uint32_t a2, uint32_t a3,
                                        uint32_t b0, uint32_t b1) {
    asm volatile("mma.sync.aligned.m16n8k16.row.col.f32.f16.f16.f32 "
                 "{%0,%1,%2,%3}, {%4,%5,%6,%7}, {%8,%9}, {%0,%1,%2,%3};"
                 : "+f"(c[0]), "+f"(c[1]), "+f"(c[2]), "+f"(c[3])
                 : "r"(a0), "r"(a1), "r"(a2), "r"(a3), "r"(b0), "r"(b1));
}
__device__ __forceinline__ void cpasync16(uint32_t dst, const void* src) {
    asm volatile("cp.async.cg.shared.global [%0], [%1], 16;" :: "r"(dst), "l"(src));
}
#define CP_COMMIT() asm volatile("cp.async.commit_group;" ::: "memory")
#define CP_WAIT2()  asm volatile("cp.async.wait_group 2;" ::: "memory")
#define CP_WAIT0()  asm volatile("cp.async.wait_group 0;" ::: "memory")

__device__ __forceinline__ uint32_t pk2(h16 a, h16 b) {
    __half2 t; t.x = a; t.y = b;
    return *reinterpret_cast<uint32_t*>(&t);
}
__device__ __forceinline__ void split2(float v, h16& h, h16& l) {
    h = __float2half_rn(v);
    l = __float2half_rn(v - __half2float(h));
}

// SMEM: 3 stages x (A[128][40] + B[128][40]) h16 = 61440 B, union with
// epilogue stg fp32 [128][132] = 67584 B
#define TPAD 40
#define SPAD 132
#define STAGE_BYTES 20480
#define SMEM_BYTES  (128 * SPAD * 4)   // 67584

// ------------------------------------------------------------------
// GroupNorm -> fp16 hi token-major [b][n][c] (B-side operand: hi only)
// ------------------------------------------------------------------
__global__ __launch_bounds__(256) void gn_kernel(const float* __restrict__ x,
                                                 const float* __restrict__ w,
                                                 const float* __restrict__ bias) {
    int b = blockIdx.x >> 5;
    int g = blockIdx.x & 31;
    size_t base = ((size_t)b * CHN + g * 8) * NTOK;
    const float4* xv = (const float4*)(x + base);
    const int NV = 8 * NTOK / 4;

    float s = 0.f, ss = 0.f;
    for (int i = threadIdx.x; i < NV; i += 256) {
        float4 v = xv[i];
        s  += v.x + v.y + v.z + v.w;
        ss += v.x*v.x + v.y*v.y + v.z*v.z + v.w*v.w;
    }
    __shared__ float rs[256], rss[256];
    rs[threadIdx.x] = s; rss[threadIdx.x] = ss;
    __syncthreads();
    for (int st = 128; st > 0; st >>= 1) {
        if (threadIdx.x < st) { rs[threadIdx.x] += rs[threadIdx.x+st]; rss[threadIdx.x] += rss[threadIdx.x+st]; }
        __syncthreads();
    }
    float mean = rs[0] * (1.f/32768.f);
    float var  = rss[0] * (1.f/32768.f) - mean*mean;
    float rstd = rsqrtf(var + EPS);

    float sc[8], sh[8];
    #pragma unroll
    for (int c = 0; c < 8; c++) {
        sc[c] = w[g*8+c] * rstd;
        sh[c] = bias[g*8+c] - mean * sc[c];
    }
    for (int it = 0; it < 16; it++) {
        int n = it * 256 + threadIdx.x;
        uint32_t hp[4];
        #pragma unroll
        for (int p = 0; p < 4; p++) {
            float v0 = x[base + (size_t)(2*p  )*NTOK + n] * sc[2*p  ] + sh[2*p  ];
            float v1 = x[base + (size_t)(2*p+1)*NTOK + n] * sc[2*p+1] + sh[2*p+1];
            hp[p] = pk2(__float2half_rn(v0), __float2half_rn(v1));
        }
        size_t off = ((size_t)(b*NTOK + n)) * CHN + g*8;
        *(uint4*)(g_xnh + off) = make_uint4(hp[0], hp[1], hp[2], hp[3]);
    }
}

// ------------------------------------------------------------------
__global__ __launch_bounds__(256) void prep_w(const float* __restrict__ qkvw,
                                              const float* __restrict__ outw) {
    int idx = blockIdx.x * 256 + threadIdx.x;
    #pragma unroll
    for (int r = 0; r < 3; r++) {
        int i = idx + r * 65536;
        h16 h, l; split2(qkvw[i], h, l);
        g_wqh[i] = h; g_wql[i] = l;
    }
    h16 h, l; split2(outw[idx], h, l);
    g_woh[idx] = h; g_wol[idx] = l;
}

// ------------------------------------------------------------------
// 2-term fp16 HMMA GEMM: D[128x128] = (Ah+Al) x Bh  over K
// 128 threads = 4 warps (2 m x 2 n); warp tile 64x64; 3-stage cp.async
// MODE 0 = QKV, 1 = scores, 2 = AV, 3 = proj
// ------------------------------------------------------------------
template<int MODE>
__global__ __launch_bounds__(128)
void tc_gemm(const float* __restrict__ bias,
             const float* __restrict__ resid,
             float* __restrict__ outf) {
    extern __shared__ char smem[];
    float* stg = (float*)smem;             // [128][132] (epilogue)
    const uint32_t sbase = smem_u32(smem);

    const int tid  = threadIdx.x;
    const int lane = tid & 31;
    const int wid  = tid >> 5;
    const int warp_m = wid & 1;            // 64-row slab
    const int warp_n = wid >> 1;           // 64-col slab
    const int b = blockIdx.z;

    const h16 *Ah, *Al, *Bh;
    int lda, ldb;
    int n0 = 0, m0 = 0, c0 = 0;
    if (MODE == 0) {
        n0 = blockIdx.x * 128; m0 = blockIdx.y * 128;
        Ah = g_wqh + (size_t)m0 * CHN;  Al = g_wql + (size_t)m0 * CHN;
        Bh = g_xnh + ((size_t)(b*NTOK + n0)) * CHN;
        lda = CHN; ldb = CHN;
    } else if (MODE == 1) {
        m0 = blockIdx.x * 128; n0 = blockIdx.y * 128;
        Ah = g_qh + ((size_t)(b*NTOK + n0)) * CHN;
        Al = g_ql + ((size_t)(b*NTOK + n0)) * CHN;
        Bh = g_kh + ((size_t)(b*NTOK + m0)) * CHN;
        lda = CHN; ldb = CHN;
    } else if (MODE == 2) {
        c0 = blockIdx.x * 128; n0 = blockIdx.y * 128;
        Ah = g_ph + ((size_t)b*NTOK + n0) * NTOK;
        Al = g_pl + ((size_t)b*NTOK + n0) * NTOK;
        Bh = g_vh + ((size_t)(b*CHN + c0)) * NTOK;
        lda = NTOK; ldb = NTOK;
    } else {
        n0 = blockIdx.x * 128; m0 = blockIdx.y * 128;
        Ah = g_woh + (size_t)m0 * CHN;  Al = g_wol + (size_t)m0 * CHN;
        Bh = g_aoh + ((size_t)(b*NTOK + n0)) * CHN;
        lda = CHN; ldb = CHN;
    }
    const int Ktot = (MODE == 2) ? NTOK : CHN;
    const int ncs  = Ktot / 32;
    const int total = 2 * ncs;             // seg 0: Ah*Bh, seg 1: Al*Bh

    float acc[4][8][4];
    #pragma unroll
    for (int i = 0; i < 4; i++)
        #pragma unroll
        for (int j = 0; j < 8; j++)
            #pragma unroll
            for (int q = 0; q < 4; q++) acc[i][j][q] = 0.f;

    const int prow = tid >> 2;           // 0..31 (+32*i)
    const int pcol = (tid & 3) * 8;      // h16 col: 0,8,16,24

    auto prefetch = [&](int cc, int s) {
        if (cc >= total) return;
        int seg = cc / ncs, rch = cc - seg * ncs;
        int kk = rch * 32;
        const h16* Ap = seg ? Al : Ah;
        uint32_t dA = sbase + s * STAGE_BYTES;
        uint32_t dB = dA + 10240;
        #pragma unroll
        for (int i = 0; i < 4; i++) {
            int row = prow + 32 * i;
            cpasync16(dA + (row * TPAD + pcol) * 2, Ap + (size_t)row * lda + kk + pcol);
            cpasync16(dB + (row * TPAD + pcol) * 2, Bh + (size_t)row * ldb + kk + pcol);
        }
    };

    prefetch(0, 0); CP_COMMIT();
    prefetch(1, 1); CP_COMMIT();
    prefetch(2, 2); CP_COMMIT();

    int s = 0;
    for (int cc = 0; cc < total; cc++) {
        CP_WAIT2();
        __syncthreads();
        const uint32_t tA = sbase + s * STAGE_BYTES;
        const uint32_t tB = tA + 10240;
        #pragma unroll
        for (int ks = 0; ks < 2; ks++) {
            uint32_t a[4][4];
            #pragma unroll
            for (int mi = 0; mi < 4; mi++) {
                uint32_t addr = tA + ((warp_m*64 + mi*16 + (lane & 15)) * TPAD
                                      + ks*16 + (lane >> 4) * 8) * 2;
                ldsm_x4(a[mi][0], a[mi][1], a[mi][2], a[mi][3], addr);
            }
            #pragma unroll
            for (int ni = 0; ni < 4; ni++) {
                uint32_t b0, b1, b2, b3;
                uint32_t addr = tB + ((warp_n*64 + ni*16 + (lane & 15)) * TPAD
                                      + ks*16 + (lane >> 4) * 8) * 2;
                ldsm_x4(b0, b1, b2, b3, addr);
                #pragma unroll
                for (int mi = 0; mi < 4; mi++) {
                    mma_f16(acc[mi][2*ni],   a[mi][0], a[mi][1], a[mi][2], a[mi][3], b0, b2);
                    mma_f16(acc[mi][2*ni+1], a[mi][0], a[mi][1], a[mi][2], a[mi][3], b1, b3);
                }
            }
        }
        __syncthreads();
        prefetch(cc + 3, s);
        CP_COMMIT();
        s = (s == 2) ? 0 : s + 1;
    }
    CP_WAIT0();
    __syncthreads();   // tiles dead; smem becomes stg

    // ---- stage accumulators to smem fp32 [128][132] ----
    #pragma unroll
    for (int mi = 0; mi < 4; mi++) {
        #pragma unroll
        for (int nj = 0; nj < 8; nj++) {
            int r = warp_m*64 + mi*16 + (lane >> 2);
            int c = warp_n*64 + nj*8 + (lane & 3) * 2;
            *(float2*)&stg[r * SPAD + c]       = make_float2(acc[mi][nj][0], acc[mi][nj][1]);
            *(float2*)&stg[(r + 8) * SPAD + c] = make_float2(acc[mi][nj][2], acc[mi][nj][3]);
        }
    }
    __syncthreads();

    // ---- writeback (128 threads; thread tid owns row tid) ----
    const int r = tid;
    if (MODE == 1) {
        float* Srow = g_attn + (size_t)b*NTOK*NTOK + (size_t)(n0 + r)*NTOK + m0;
        #pragma unroll
        for (int j = 0; j < 128; j += 4) {
            float4 o = make_float4(stg[r*SPAD + j]     * 0.0625f,
                                   stg[r*SPAD + j + 1] * 0.0625f,
                                   stg[r*SPAD + j + 2] * 0.0625f,
                                   stg[r*SPAD + j + 3] * 0.0625f);
            *(float4*)(Srow + j) = o;
        }
    } else if (MODE == 2) {     // ao: hi only (B of proj)
        h16* Hr = g_aoh + ((size_t)(b*NTOK + n0 + r)) * CHN + c0;
        #pragma unroll
        for (int j0 = 0; j0 < 128; j0 += 8) {
            uint32_t h4[4];
            #pragma unroll
            for (int p = 0; p < 4; p++)
                h4[p] = pk2(__float2half_rn(stg[r*SPAD + j0 + 2*p]),
                            __float2half_rn(stg[r*SPAD + j0 + 2*p + 1]));
            *(uint4*)(Hr + j0) = make_uint4(h4[0],h4[1],h4[2],h4[3]);
        }
    } else if (MODE == 3) {
        size_t roff = ((size_t)(b*CHN + m0 + r)) * NTOK + n0;
        float bb = bias[m0 + r];
        #pragma unroll
        for (int j = 0; j < 128; j += 4) {
            float4 rr = *(const float4*)(resid + roff + j);
            float4 o = make_float4(stg[r*SPAD + j]     + bb + rr.x,
                                   stg[r*SPAD + j + 1] + bb + rr.y,
                                   stg[r*SPAD + j + 2] + bb + rr.z,
                                   stg[r*SPAD + j + 3] + bb + rr.w);
            *(float4*)(outf + roff + j) = o;
        }
    } else {  // MODE 0
        if (m0 >= 512) {   // V rows: [c][m], hi only
            float bb = bias[m0 + r];
            h16* Hr = g_vh + ((size_t)(b*CHN + m0 - 512 + r)) * NTOK + n0;
            #pragma unroll
            for (int j0 = 0; j0 < 128; j0 += 8) {
                uint32_t h4[4];
                #pragma unroll
                for (int p = 0; p < 4; p++)
                    h4[p] = pk2(__float2half_rn(stg[r*SPAD + j0 + 2*p]     + bb),
                                __float2half_rn(stg[r*SPAD + j0 + 2*p + 1] + bb));
                *(uint4*)(Hr + j0) = make_uint4(h4[0],h4[1],h4[2],h4[3]);
            }
        } else {           // Q (hi+lo) / K (hi): transpose to [n][c] + bias
            const bool isQ = (m0 < 256);
            h16* dsth = (isQ ? g_qh : g_kh) + ((size_t)b*NTOK) * CHN;
            h16* dstl = g_ql + ((size_t)b*NTOK) * CHN;
            int obase = m0 & 255;
            #pragma unroll
            for (int it = 0; it < 16; it++) {
                int lin = tid + it * 128;
                int j  = lin >> 4;      // token col 0..127
                int ck = lin & 15;      // 8-channel chunk
                uint32_t h4[4], l4[4];
                #pragma unroll
                for (int p = 0; p < 4; p++) {
                    float v0 = stg[(ck*8 + 2*p    ) * SPAD + j] + bias[m0 + ck*8 + 2*p];
                    float v1 = stg[(ck*8 + 2*p + 1) * SPAD + j] + bias[m0 + ck*8 + 2*p + 1];
                    h16 h0,l0,h1,l1; split2(v0,h0,l0); split2(v1,h1,l1);
                    h4[p] = pk2(h0,h1); l4[p] = pk2(l0,l1);
                }
                size_t off = ((size_t)(n0 + j)) * CHN + obase + ck*8;
                *(uint4*)(dsth + off) = make_uint4(h4[0],h4[1],h4[2],h4[3]);
                if (isQ)
                    *(uint4*)(dstl + off) = make_uint4(l4[0],l4[1],l4[2],l4[3]);
            }
        }
    }
}

// ------------------------------------------------------------------
// softmax: fp32 scores row -> fp16 hi/lo probs (A of AV)
// ------------------------------------------------------------------
__global__ __launch_bounds__(256) void softmax_kernel() {
    size_t row = blockIdx.x;
    const float4* pv = (const float4*)(g_attn + row * NTOK);
    uint2* ph = (uint2*)(g_ph + row * NTOK);
    uint2* pl = (uint2*)(g_pl + row * NTOK);
    const int t = threadIdx.x;
    float4 v[4];
    float mx = -1e30f;
    #pragma unroll
    for (int i = 0; i < 4; i++) {
        v[i] = pv[t + i*256];
        mx = fmaxf(mx, fmaxf(fmaxf(v[i].x, v[i].y), fmaxf(v[i].z, v[i].w)));
    }
    __shared__ float red[256];
    red[t] = mx; __syncthreads();
    for (int st = 128; st > 0; st >>= 1) {
        if (t < st) red[t] = fmaxf(red[t], red[t+st]);
        __syncthreads();
    }
    mx = red[0];
    __syncthreads();
    float s = 0.f;
    #pragma unroll
    for (int i = 0; i < 4; i++) {
        v[i].x = __expf(v[i].x - mx); v[i].y = __expf(v[i].y - mx);
        v[i].z = __expf(v[i].z - mx); v[i].w = __expf(v[i].w - mx);
        s += v[i].x + v[i].y + v[i].z + v[i].w;
    }
    red[t] = s; __syncthreads();
    for (int st = 128; st > 0; st >>= 1) {
        if (t < st) red[t] += red[t+st];
        __syncthreads();
    }
    float inv = 1.f / red[0];
    #pragma unroll
    for (int i = 0; i < 4; i++) {
        float a0 = v[i].x*inv, a1 = v[i].y*inv, a2 = v[i].z*inv, a3 = v[i].w*inv;
        h16 h0,l0,h1,l1,h2,l2,h3,l3;
        split2(a0,h0,l0); split2(a1,h1,l1); split2(a2,h2,l2); split2(a3,h3,l3);
        ph[t + i*256] = make_uint2(pk2(h0,h1), pk2(h2,h3));
        pl[t + i*256] = make_uint2(pk2(l0,l1), pk2(l2,l3));
    }
}

// ------------------------------------------------------------------
extern "C" void kernel_launch(void* const* d_in, const int* in_sizes, int n_in,
                              void* d_out, int out_size) {
    const float* x    = (const float*)d_in[0];
    const float* gnw  = (const float*)d_in[1];
    const float* gnb  = (const float*)d_in[2];
    const float* qkvw = (const float*)d_in[3];
    const float* qkvb = (const float*)d_in[4];
    const float* ow   = (const float*)d_in[5];
    const float* ob   = (const float*)d_in[6];
    float* y = (float*)d_out;

    cudaFuncSetAttribute(tc_gemm<0>, cudaFuncAttributeMaxDynamicSharedMemorySize, SMEM_BYTES);
    cudaFuncSetAttribute(tc_gemm<1>, cudaFuncAttributeMaxDynamicSharedMemorySize, SMEM_BYTES);
    cudaFuncSetAttribute(tc_gemm<2>, cudaFuncAttributeMaxDynamicSharedMemorySize, SMEM_BYTES);
    cudaFuncSetAttribute(tc_gemm<3>, cudaFuncAttributeMaxDynamicSharedMemorySize, SMEM_BYTES);

    prep_w   <<<256, 256>>>(qkvw, ow);
    gn_kernel<<<BATCH*32, 256>>>(x, gnw, gnb);
    tc_gemm<0><<<dim3(NTOK/128, 6, BATCH), 128, SMEM_BYTES>>>(qkvb, nullptr, nullptr);
    tc_gemm<1><<<dim3(NTOK/128, NTOK/128, BATCH), 128, SMEM_BYTES>>>(nullptr, nullptr, nullptr);
    softmax_kernel<<<BATCH*NTOK, 256>>>();
    tc_gemm<2><<<dim3(CHN/128, NTOK/128, BATCH), 128, SMEM_BYTES>>>(nullptr, nullptr, nullptr);
    tc_gemm<3><<<dim3(NTOK/128, CHN/128, BATCH), 128, SMEM_BYTES>>>(ob, x, y);
}

// round 6
// speedup vs baseline: 5.0014x; 1.6984x over previous
#include <cuda_runtime.h>
#include <cuda_fp16.h>
#include <cstdint>

#define BATCH 4
#define CHN   256
#define NTOK  4096
#define EPS   1e-5f

typedef __half h16;

// ------------------------------------------------------------------
// scratch (__device__ globals; no allocations allowed) — all fp16
// ------------------------------------------------------------------
__device__ h16 g_xn[(size_t)BATCH*NTOK*CHN];     // groupnormed x [b][n][c]
__device__ h16 g_q [(size_t)BATCH*NTOK*CHN];     // Q [b][n][c]
__device__ h16 g_k [(size_t)BATCH*NTOK*CHN];     // K [b][m][c]
__device__ h16 g_v [(size_t)BATCH*CHN*NTOK];     // V [b][c][m]
__device__ h16 g_s [(size_t)BATCH*NTOK*NTOK];    // scores fp16 [b][n][m]
__device__ h16 g_p [(size_t)BATCH*NTOK*NTOK];    // probs fp16 [b][n][m]
__device__ h16 g_ao[(size_t)BATCH*NTOK*CHN];     // attn-out [b][n][c]
__device__ h16 g_wq[3*CHN*CHN];
__device__ h16 g_wo[CHN*CHN];

// ------------------------------------------------------------------
__device__ __forceinline__ uint32_t smem_u32(const void* p) {
    uint32_t a;
    asm("{ .reg .u64 t; cvta.to.shared.u64 t, %1; cvt.u32.u64 %0, t; }" : "=r"(a) : "l"(p));
    return a;
}
__device__ __forceinline__ void ldsm_x4(uint32_t& r0, uint32_t& r1, uint32_t& r2,
                                        uint32_t& r3, uint32_t addr) {
    asm volatile("ldmatrix.sync.aligned.m8n8.x4.shared.b16 {%0,%1,%2,%3}, [%4];"
                 : "=r"(r0), "=r"(r1), "=r"(r2), "=r"(r3) : "r"(addr));
}
__device__ __forceinline__ void mma_f16(float* c, uint32_t a0, uint32_t a1,
                                        uint32_t a2, uint32_t a3,
                                        uint32_t b0, uint32_t b1) {
    asm volatile("mma.sync.aligned.m16n8k16.row.col.f32.f16.f16.f32 "
                 "{%0,%1,%2,%3}, {%4,%5,%6,%7}, {%8,%9}, {%0,%1,%2,%3};"
                 : "+f"(c[0]), "+f"(c[1]), "+f"(c[2]), "+f"(c[3])
                 : "r"(a0), "r"(a1), "r"(a2), "r"(a3), "r"(b0), "r"(b1));
}
__device__ __forceinline__ void cpasync16(uint32_t dst, const void* src) {
    asm volatile("cp.async.cg.shared.global [%0], [%1], 16;" :: "r"(dst), "l"(src));
}
#define CP_COMMIT() asm volatile("cp.async.commit_group;" ::: "memory")
#define CP_WAIT2()  asm volatile("cp.async.wait_group 2;" ::: "memory")
#define CP_WAIT0()  asm volatile("cp.async.wait_group 0;" ::: "memory")

__device__ __forceinline__ uint32_t pk2(h16 a, h16 b) {
    __half2 t; t.x = a; t.y = b;
    return *reinterpret_cast<uint32_t*>(&t);
}

// SMEM: 3 stages x (A[128][40] + B[128][40]) h16 = 61440 B, union with
// epilogue stg fp32 [128][132] = 67584 B
#define TPAD 40
#define SPAD 132
#define STAGE_BYTES 20480
#define SMEM_BYTES  (128 * SPAD * 4)   // 67584

// ------------------------------------------------------------------
// GroupNorm -> fp16 token-major [b][n][c]
// ------------------------------------------------------------------
__global__ __launch_bounds__(256) void gn_kernel(const float* __restrict__ x,
                                                 const float* __restrict__ w,
                                                 const float* __restrict__ bias) {
    int b = blockIdx.x >> 5;
    int g = blockIdx.x & 31;
    size_t base = ((size_t)b * CHN + g * 8) * NTOK;
    const float4* xv = (const float4*)(x + base);
    const int NV = 8 * NTOK / 4;

    float s = 0.f, ss = 0.f;
    for (int i = threadIdx.x; i < NV; i += 256) {
        float4 v = xv[i];
        s  += v.x + v.y + v.z + v.w;
        ss += v.x*v.x + v.y*v.y + v.z*v.z + v.w*v.w;
    }
    __shared__ float rs[256], rss[256];
    rs[threadIdx.x] = s; rss[threadIdx.x] = ss;
    __syncthreads();
    for (int st = 128; st > 0; st >>= 1) {
        if (threadIdx.x < st) { rs[threadIdx.x] += rs[threadIdx.x+st]; rss[threadIdx.x] += rss[threadIdx.x+st]; }
        __syncthreads();
    }
    float mean = rs[0] * (1.f/32768.f);
    float var  = rss[0] * (1.f/32768.f) - mean*mean;
    float rstd = rsqrtf(var + EPS);

    float sc[8], sh[8];
    #pragma unroll
    for (int c = 0; c < 8; c++) {
        sc[c] = w[g*8+c] * rstd;
        sh[c] = bias[g*8+c] - mean * sc[c];
    }
    for (int it = 0; it < 16; it++) {
        int n = it * 256 + threadIdx.x;
        uint32_t hp[4];
        #pragma unroll
        for (int p = 0; p < 4; p++) {
            float v0 = x[base + (size_t)(2*p  )*NTOK + n] * sc[2*p  ] + sh[2*p  ];
            float v1 = x[base + (size_t)(2*p+1)*NTOK + n] * sc[2*p+1] + sh[2*p+1];
            hp[p] = pk2(__float2half_rn(v0), __float2half_rn(v1));
        }
        size_t off = ((size_t)(b*NTOK + n)) * CHN + g*8;
        *(uint4*)(g_xn + off) = make_uint4(hp[0], hp[1], hp[2], hp[3]);
    }
}

// ------------------------------------------------------------------
__global__ __launch_bounds__(256) void prep_w(const float* __restrict__ qkvw,
                                              const float* __restrict__ outw) {
    int idx = blockIdx.x * 256 + threadIdx.x;
    #pragma unroll
    for (int r = 0; r < 3; r++) {
        int i = idx + r * 65536;
        g_wq[i] = __float2half_rn(qkvw[i]);
    }
    g_wo[idx] = __float2half_rn(outw[idx]);
}

// ------------------------------------------------------------------
// single-term fp16 HMMA GEMM: D[128x128] = A x B^T over K
// 128 threads = 4 warps (2 m x 2 n); warp tile 64x64; 3-stage cp.async
// MODE 0 = QKV, 1 = scores, 2 = AV, 3 = proj
// ------------------------------------------------------------------
template<int MODE>
__global__ __launch_bounds__(128)
void tc_gemm(const float* __restrict__ bias,
             const float* __restrict__ resid,
             float* __restrict__ outf) {
    extern __shared__ char smem[];
    float* stg = (float*)smem;             // [128][132] (epilogue)
    const uint32_t sbase = smem_u32(smem);

    const int tid  = threadIdx.x;
    const int lane = tid & 31;
    const int wid  = tid >> 5;
    const int warp_m = wid & 1;            // 64-row slab
    const int warp_n = wid >> 1;           // 64-col slab
    const int b = blockIdx.z;

    const h16 *A, *B;
    int lda, ldb;
    int n0 = 0, m0 = 0, c0 = 0;
    if (MODE == 0) {
        n0 = blockIdx.x * 128; m0 = blockIdx.y * 128;
        A = g_wq + (size_t)m0 * CHN;
        B = g_xn + ((size_t)(b*NTOK + n0)) * CHN;
        lda = CHN; ldb = CHN;
    } else if (MODE == 1) {
        m0 = blockIdx.x * 128; n0 = blockIdx.y * 128;
        A = g_q + ((size_t)(b*NTOK + n0)) * CHN;
        B = g_k + ((size_t)(b*NTOK + m0)) * CHN;
        lda = CHN; ldb = CHN;
    } else if (MODE == 2) {
        c0 = blockIdx.x * 128; n0 = blockIdx.y * 128;
        A = g_p + ((size_t)b*NTOK + n0) * NTOK;
        B = g_v + ((size_t)(b*CHN + c0)) * NTOK;
        lda = NTOK; ldb = NTOK;
    } else {
        n0 = blockIdx.x * 128; m0 = blockIdx.y * 128;
        A = g_wo + (size_t)m0 * CHN;
        B = g_ao + ((size_t)(b*NTOK + n0)) * CHN;
        lda = CHN; ldb = CHN;
    }
    const int Ktot = (MODE == 2) ? NTOK : CHN;
    const int total = Ktot / 32;

    float acc[4][8][4];
    #pragma unroll
    for (int i = 0; i < 4; i++)
        #pragma unroll
        for (int j = 0; j < 8; j++)
            #pragma unroll
            for (int q = 0; q < 4; q++) acc[i][j][q] = 0.f;

    const int prow = tid >> 2;           // 0..31 (+32*i)
    const int pcol = (tid & 3) * 8;      // h16 col: 0,8,16,24

    auto prefetch = [&](int cc, int s) {
        if (cc >= total) return;
        int kk = cc * 32;
        uint32_t dA = sbase + s * STAGE_BYTES;
        uint32_t dB = dA + 10240;
        #pragma unroll
        for (int i = 0; i < 4; i++) {
            int row = prow + 32 * i;
            cpasync16(dA + (row * TPAD + pcol) * 2, A + (size_t)row * lda + kk + pcol);
            cpasync16(dB + (row * TPAD + pcol) * 2, B + (size_t)row * ldb + kk + pcol);
        }
    };

    prefetch(0, 0); CP_COMMIT();
    prefetch(1, 1); CP_COMMIT();
    prefetch(2, 2); CP_COMMIT();

    int s = 0;
    for (int cc = 0; cc < total; cc++) {
        CP_WAIT2();
        __syncthreads();
        const uint32_t tA = sbase + s * STAGE_BYTES;
        const uint32_t tB = tA + 10240;
        #pragma unroll
        for (int ks = 0; ks < 2; ks++) {
            uint32_t a[4][4];
            #pragma unroll
            for (int mi = 0; mi < 4; mi++) {
                uint32_t addr = tA + ((warp_m*64 + mi*16 + (lane & 15)) * TPAD
                                      + ks*16 + (lane >> 4) * 8) * 2;
                ldsm_x4(a[mi][0], a[mi][1], a[mi][2], a[mi][3], addr);
            }
            #pragma unroll
            for (int ni = 0; ni < 4; ni++) {
                uint32_t b0, b1, b2, b3;
                uint32_t addr = tB + ((warp_n*64 + ni*16 + (lane & 15)) * TPAD
                                      + ks*16 + (lane >> 4) * 8) * 2;
                ldsm_x4(b0, b1, b2, b3, addr);
                #pragma unroll
                for (int mi = 0; mi < 4; mi++) {
                    mma_f16(acc[mi][2*ni],   a[mi][0], a[mi][1], a[mi][2], a[mi][3], b0, b2);
                    mma_f16(acc[mi][2*ni+1], a[mi][0], a[mi][1], a[mi][2], a[mi][3], b1, b3);
                }
            }
        }
        __syncthreads();
        prefetch(cc + 3, s);
        CP_COMMIT();
        s = (s == 2) ? 0 : s + 1;
    }
    CP_WAIT0();
    __syncthreads();   // tiles dead; smem becomes stg

    // ---- stage accumulators to smem fp32 [128][132] ----
    #pragma unroll
    for (int mi = 0; mi < 4; mi++) {
        #pragma unroll
        for (int nj = 0; nj < 8; nj++) {
            int r = warp_m*64 + mi*16 + (lane >> 2);
            int c = warp_n*64 + nj*8 + (lane & 3) * 2;
            *(float2*)&stg[r * SPAD + c]       = make_float2(acc[mi][nj][0], acc[mi][nj][1]);
            *(float2*)&stg[(r + 8) * SPAD + c] = make_float2(acc[mi][nj][2], acc[mi][nj][3]);
        }
    }
    __syncthreads();

    // ---- writeback (128 threads; thread tid owns row tid) ----
    const int r = tid;
    if (MODE == 1) {          // scores -> fp16 * scale
        h16* Srow = g_s + (size_t)b*NTOK*NTOK + (size_t)(n0 + r)*NTOK + m0;
        #pragma unroll
        for (int j0 = 0; j0 < 128; j0 += 8) {
            uint32_t h4[4];
            #pragma unroll
            for (int p = 0; p < 4; p++)
                h4[p] = pk2(__float2half_rn(stg[r*SPAD + j0 + 2*p]     * 0.0625f),
                            __float2half_rn(stg[r*SPAD + j0 + 2*p + 1] * 0.0625f));
            *(uint4*)(Srow + j0) = make_uint4(h4[0],h4[1],h4[2],h4[3]);
        }
    } else if (MODE == 2) {   // ao fp16
        h16* Hr = g_ao + ((size_t)(b*NTOK + n0 + r)) * CHN + c0;
        #pragma unroll
        for (int j0 = 0; j0 < 128; j0 += 8) {
            uint32_t h4[4];
            #pragma unroll
            for (int p = 0; p < 4; p++)
                h4[p] = pk2(__float2half_rn(stg[r*SPAD + j0 + 2*p]),
                            __float2half_rn(stg[r*SPAD + j0 + 2*p + 1]));
            *(uint4*)(Hr + j0) = make_uint4(h4[0],h4[1],h4[2],h4[3]);
        }
    } else if (MODE == 3) {   // out = proj + bias + residual (fp32)
        size_t roff = ((size_t)(b*CHN + m0 + r)) * NTOK + n0;
        float bb = bias[m0 + r];
        #pragma unroll
        for (int j = 0; j < 128; j += 4) {
            float4 rr = *(const float4*)(resid + roff + j);
            float4 o = make_float4(stg[r*SPAD + j]     + bb + rr.x,
                                   stg[r*SPAD + j + 1] + bb + rr.y,
                                   stg[r*SPAD + j + 2] + bb + rr.z,
                                   stg[r*SPAD + j + 3] + bb + rr.w);
            *(float4*)(outf + roff + j) = o;
        }
    } else {  // MODE 0
        if (m0 >= 512) {   // V rows: [c][m] + bias
            float bb = bias[m0 + r];
            h16* Hr = g_v + ((size_t)(b*CHN + m0 - 512 + r)) * NTOK + n0;
            #pragma unroll
            for (int j0 = 0; j0 < 128; j0 += 8) {
                uint32_t h4[4];
                #pragma unroll
                for (int p = 0; p < 4; p++)
                    h4[p] = pk2(__float2half_rn(stg[r*SPAD + j0 + 2*p]     + bb),
                                __float2half_rn(stg[r*SPAD + j0 + 2*p + 1] + bb));
                *(uint4*)(Hr + j0) = make_uint4(h4[0],h4[1],h4[2],h4[3]);
            }
        } else {           // Q / K: transpose to [n][c] + bias
            h16* dst = ((m0 < 256) ? g_q : g_k) + ((size_t)b*NTOK) * CHN;
            int obase = m0 & 255;
            #pragma unroll
            for (int it = 0; it < 16; it++) {
                int lin = tid + it * 128;
                int j  = lin >> 4;      // token col 0..127
                int ck = lin & 15;      // 8-channel chunk
                uint32_t h4[4];
                #pragma unroll
                for (int p = 0; p < 4; p++) {
                    float v0 = stg[(ck*8 + 2*p    ) * SPAD + j] + bias[m0 + ck*8 + 2*p];
                    float v1 = stg[(ck*8 + 2*p + 1) * SPAD + j] + bias[m0 + ck*8 + 2*p + 1];
                    h4[p] = pk2(__float2half_rn(v0), __float2half_rn(v1));
                }
                size_t off = ((size_t)(n0 + j)) * CHN + obase + ck*8;
                *(uint4*)(dst + off) = make_uint4(h4[0],h4[1],h4[2],h4[3]);
            }
        }
    }
}

// ------------------------------------------------------------------
// softmax: fp16 scores row -> fp16 probs
// ------------------------------------------------------------------
__global__ __launch_bounds__(256) void softmax_kernel() {
    size_t row = blockIdx.x;
    const uint4* pv = (const uint4*)(g_s + row * NTOK);  // 512 uint4/row
    uint4* pp = (uint4*)(g_p + row * NTOK);
    const int t = threadIdx.x;

    uint4 raw[2];
    float v[16];
    float mx = -1e30f;
    #pragma unroll
    for (int i = 0; i < 2; i++) {
        raw[i] = pv[t + i*256];
        const uint32_t* u = (const uint32_t*)&raw[i];
        #pragma unroll
        for (int q = 0; q < 4; q++) {
            __half2 h2 = *reinterpret_cast<const __half2*>(&u[q]);
            float2 f = __half22float2(h2);
            v[i*8 + 2*q]     = f.x;
            v[i*8 + 2*q + 1] = f.y;
            mx = fmaxf(mx, fmaxf(f.x, f.y));
        }
    }
    __shared__ float red[256];
    red[t] = mx; __syncthreads();
    for (int st = 128; st > 0; st >>= 1) {
        if (t < st) red[t] = fmaxf(red[t], red[t+st]);
        __syncthreads();
    }
    mx = red[0];
    __syncthreads();
    float s = 0.f;
    #pragma unroll
    for (int i = 0; i < 16; i++) {
        v[i] = __expf(v[i] - mx);
        s += v[i];
    }
    red[t] = s; __syncthreads();
    for (int st = 128; st > 0; st >>= 1) {
        if (t < st) red[t] += red[t+st];
        __syncthreads();
    }
    float inv = 1.f / red[0];
    #pragma unroll
    for (int i = 0; i < 2; i++) {
        uint32_t h4[4];
        #pragma unroll
        for (int q = 0; q < 4; q++)
            h4[q] = pk2(__float2half_rn(v[i*8 + 2*q] * inv),
                        __float2half_rn(v[i*8 + 2*q + 1] * inv));
        pp[t + i*256] = make_uint4(h4[0], h4[1], h4[2], h4[3]);
    }
}

// ------------------------------------------------------------------
extern "C" void kernel_launch(void* const* d_in, const int* in_sizes, int n_in,
                              void* d_out, int out_size) {
    const float* x    = (const float*)d_in[0];
    const float* gnw  = (const float*)d_in[1];
    const float* gnb  = (const float*)d_in[2];
    const float* qkvw = (const float*)d_in[3];
    const float* qkvb = (const float*)d_in[4];
    const float* ow   = (const float*)d_in[5];
    const float* ob   = (const float*)d_in[6];
    float* y = (float*)d_out;

    cudaFuncSetAttribute(tc_gemm<0>, cudaFuncAttributeMaxDynamicSharedMemorySize, SMEM_BYTES);
    cudaFuncSetAttribute(tc_gemm<1>, cudaFuncAttributeMaxDynamicSharedMemorySize, SMEM_BYTES);
    cudaFuncSetAttribute(tc_gemm<2>, cudaFuncAttributeMaxDynamicSharedMemorySize, SMEM_BYTES);
    cudaFuncSetAttribute(tc_gemm<3>, cudaFuncAttributeMaxDynamicSharedMemorySize, SMEM_BYTES);

    prep_w   <<<256, 256>>>(qkvw, ow);
    gn_kernel<<<BATCH*32, 256>>>(x, gnw, gnb);
    tc_gemm<0><<<dim3(NTOK/128, 6, BATCH), 128, SMEM_BYTES>>>(qkvb, nullptr, nullptr);
    tc_gemm<1><<<dim3(NTOK/128, NTOK/128, BATCH), 128, SMEM_BYTES>>>(nullptr, nullptr, nullptr);
    softmax_kernel<<<BATCH*NTOK, 256>>>();
    tc_gemm<2><<<dim3(CHN/128, NTOK/128, BATCH), 128, SMEM_BYTES>>>(nullptr, nullptr, nullptr);
    tc_gemm<3><<<dim3(NTOK/128, CHN/128, BATCH), 128, SMEM_BYTES>>>(ob, x, y);
}